// round 1
// baseline (speedup 1.0000x reference)
#include <cuda_runtime.h>
#include <math.h>

#define BB    2
#define TT    2048
#define DIMM  1024
#define HH    16
#define DHH   64
#define MROWS (BB * TT)        // 4096
#define QKVN  (3 * DIMM)       // 3072
#define SP    68               // padded smem row stride (floats)

// Scratch (allocation-free rule: __device__ globals)
__device__ float g_qkv[(size_t)MROWS * QKVN];   // [4096, 3072] q|k|v
__device__ float g_y[(size_t)MROWS * DIMM];     // attention output [4096, 1024]

// ---------------------------------------------------------------------------
// SGEMM: C[M,N] = A[M,K] @ Bm[K,N] + bias[N]
// 128x128 block tile, BK=8, 256 threads, 8x8 per thread (2x2 quadrants of 4),
// register double-buffered global prefetch.
// Requires M%128==0, N%128==0, K%8==0 (true for all uses here).
// ---------------------------------------------------------------------------
__global__ __launch_bounds__(256, 2)
void sgemm_bias_kernel(const float* __restrict__ A, const float* __restrict__ Bm,
                       const float* __restrict__ bias, float* __restrict__ C,
                       int M, int N, int K)
{
    __shared__ float As[8][128];   // transposed: As[k][m]
    __shared__ float Bs[8][128];   // Bs[k][n]

    const int tid = threadIdx.x;
    const int tx  = tid & 15;
    const int ty  = tid >> 4;
    const int m0  = blockIdx.y * 128;
    const int n0  = blockIdx.x * 128;

    const int arow = tid >> 1;          // 0..127
    const int acol = (tid & 1) << 2;    // 0 or 4
    const int brow = tid >> 5;          // 0..7
    const int bcol = (tid & 31) << 2;   // 0..124

    float acc[8][8];
#pragma unroll
    for (int i = 0; i < 8; i++)
#pragma unroll
        for (int j = 0; j < 8; j++) acc[i][j] = 0.f;

    const float* Aptr = A + (size_t)(m0 + arow) * K + acol;
    const float* Bptr = Bm + (size_t)brow * N + n0 + bcol;

    float4 av = *(const float4*)Aptr;
    float4 bv = *(const float4*)Bptr;

    const int ntiles = K >> 3;
    for (int kt = 0; kt < ntiles; kt++) {
        As[acol + 0][arow] = av.x;
        As[acol + 1][arow] = av.y;
        As[acol + 2][arow] = av.z;
        As[acol + 3][arow] = av.w;
        *(float4*)&Bs[brow][bcol] = bv;
        __syncthreads();

        if (kt + 1 < ntiles) {
            av = *(const float4*)(Aptr + (size_t)(kt + 1) * 8);
            bv = *(const float4*)(Bptr + (size_t)(kt + 1) * 8 * N);
        }

#pragma unroll
        for (int k = 0; k < 8; k++) {
            float a[8], b[8];
            *(float4*)&a[0] = *(const float4*)&As[k][(ty << 2)];
            *(float4*)&a[4] = *(const float4*)&As[k][64 + (ty << 2)];
            *(float4*)&b[0] = *(const float4*)&Bs[k][(tx << 2)];
            *(float4*)&b[4] = *(const float4*)&Bs[k][64 + (tx << 2)];
#pragma unroll
            for (int i = 0; i < 8; i++)
#pragma unroll
                for (int j = 0; j < 8; j++)
                    acc[i][j] += a[i] * b[j];
        }
        __syncthreads();
    }

    // Epilogue: rows {4ty+i, 64+4ty+i}, cols {4tx+j, 64+4tx+j}
#pragma unroll
    for (int ih = 0; ih < 2; ih++) {
#pragma unroll
        for (int i = 0; i < 4; i++) {
            int r = m0 + ih * 64 + (ty << 2) + i;
            float* Crow = C + (size_t)r * N + n0;
#pragma unroll
            for (int jh = 0; jh < 2; jh++) {
                int c = jh * 64 + (tx << 2);
                float4 o;
                o.x = acc[ih * 4 + i][jh * 4 + 0] + bias[n0 + c + 0];
                o.y = acc[ih * 4 + i][jh * 4 + 1] + bias[n0 + c + 1];
                o.z = acc[ih * 4 + i][jh * 4 + 2] + bias[n0 + c + 2];
                o.w = acc[ih * 4 + i][jh * 4 + 3] + bias[n0 + c + 3];
                *(float4*)&Crow[c] = o;
            }
        }
    }
}

// ---------------------------------------------------------------------------
// RoPE in-place on q and k slices of qkv. Angles in fp64 (closer to truth
// than the fp32 reference's own rounding).
// One thread per (row, head, d in [0,32)).
// ---------------------------------------------------------------------------
__global__ void rope_kernel(float* __restrict__ qkv)
{
    int idx = blockIdx.x * blockDim.x + threadIdx.x;
    if (idx >= MROWS * HH * 32) return;
    int d = idx & 31;
    int h = (idx >> 5) & (HH - 1);
    int m = idx >> 9;
    int t = m & (TT - 1);

    double inv = pow(10000.0, -(double)d / 32.0);
    double ang = (double)t * inv;
    float c = (float)cos(ang);
    float s = (float)sin(ang);

    float* qp = qkv + (size_t)m * QKVN + h * DHH;
    float a = qp[d], b2 = qp[32 + d];
    qp[d]      = a * c - b2 * s;
    qp[32 + d] = a * s + b2 * c;

    float* kp = qp + DIMM;
    a = kp[d]; b2 = kp[32 + d];
    kp[d]      = a * c - b2 * s;
    kp[32 + d] = a * s + b2 * c;
}

// ---------------------------------------------------------------------------
// Flash attention (causal), fp32. BQ=BK=64, DH=64, 256 threads.
// Thread (ty,tx) owns S rows 4ty..4ty+3, cols 4tx..4tx+3.
// K stored transposed in smem (Kt[d][kcol]) for conflict-free reads.
// Dynamic smem: 4 tiles of 64*SP floats = 69632 B.
// ---------------------------------------------------------------------------
__global__ __launch_bounds__(256, 2)
void attn_kernel(const float* __restrict__ qkv, float* __restrict__ y)
{
    extern __shared__ float sm[];
    float* Qs = sm;               // [64 rows][SP] (q rows x dims)
    float* Kt = sm + 64 * SP;     // [64 dims][SP] (transposed K)
    float* Vs = sm + 2 * 64 * SP; // [64 kv  ][SP] (kv rows x dims)
    float* Ps = sm + 3 * 64 * SP; // [64 rows][SP] (probabilities)

    const int qb  = blockIdx.x;
    const int h   = blockIdx.y;
    const int b   = blockIdx.z;
    const int tid = threadIdx.x;
    const int tx  = tid & 15;
    const int ty  = tid >> 4;

    const float* base = qkv + (size_t)b * TT * QKVN + h * DHH;

    // Load Q tile once
#pragma unroll
    for (int l = 0; l < 4; l++) {
        int idx = tid + l * 256;
        int r   = idx >> 4;
        int c4  = (idx & 15) << 2;
        *(float4*)&Qs[r * SP + c4] =
            *(const float4*)&base[(size_t)((qb << 6) + r) * QKVN + c4];
    }

    float mrow[4], lrow[4], O[4][4];
#pragma unroll
    for (int i = 0; i < 4; i++) {
        mrow[i] = -1e30f;
        lrow[i] = 0.f;
#pragma unroll
        for (int j = 0; j < 4; j++) O[i][j] = 0.f;
    }

    for (int kb = 0; kb <= qb; kb++) {
        __syncthreads();   // previous PV done reading Vs; Qs visible (iter 0)

        // Load K (transposed into Kt) and V tiles
#pragma unroll
        for (int l = 0; l < 4; l++) {
            int idx = tid + l * 256;
            int r   = idx >> 4;
            int c4  = (idx & 15) << 2;
            size_t g = (size_t)((kb << 6) + r) * QKVN + c4;
            float4 k4 = *(const float4*)&base[DIMM + g];
            Kt[(c4 + 0) * SP + r] = k4.x;
            Kt[(c4 + 1) * SP + r] = k4.y;
            Kt[(c4 + 2) * SP + r] = k4.z;
            Kt[(c4 + 3) * SP + r] = k4.w;
            *(float4*)&Vs[r * SP + c4] = *(const float4*)&base[2 * DIMM + g];
        }
        __syncthreads();

        // S = (Q K^T) * DH^-0.5
        float s[4][4];
#pragma unroll
        for (int i = 0; i < 4; i++)
#pragma unroll
            for (int j = 0; j < 4; j++) s[i][j] = 0.f;

#pragma unroll
        for (int d0 = 0; d0 < 64; d0 += 4) {
            float q[4][4], kk[4][4];
#pragma unroll
            for (int i = 0; i < 4; i++)
                *(float4*)&q[i][0] = *(const float4*)&Qs[((ty << 2) + i) * SP + d0];
#pragma unroll
            for (int dd = 0; dd < 4; dd++)
                *(float4*)&kk[dd][0] = *(const float4*)&Kt[(d0 + dd) * SP + (tx << 2)];
#pragma unroll
            for (int i = 0; i < 4; i++)
#pragma unroll
                for (int dd = 0; dd < 4; dd++)
#pragma unroll
                    for (int j = 0; j < 4; j++)
                        s[i][j] += q[i][dd] * kk[dd][j];
        }

        const bool diag = (kb == qb);
#pragma unroll
        for (int i = 0; i < 4; i++)
#pragma unroll
            for (int j = 0; j < 4; j++) {
                s[i][j] *= 0.125f;  // DH^-0.5 = 1/8
                if (diag && ((tx << 2) + j) > ((ty << 2) + i))
                    s[i][j] = -1e30f;
            }

        // Online softmax (per-row, replicated across the 16 tx lanes)
#pragma unroll
        for (int i = 0; i < 4; i++) {
            float rm = fmaxf(fmaxf(s[i][0], s[i][1]), fmaxf(s[i][2], s[i][3]));
#pragma unroll
            for (int off = 8; off > 0; off >>= 1)
                rm = fmaxf(rm, __shfl_xor_sync(0xffffffffu, rm, off, 16));
            float mn    = fmaxf(mrow[i], rm);
            float alpha = __expf(mrow[i] - mn);
            float rs    = 0.f;
#pragma unroll
            for (int j = 0; j < 4; j++) {
                float p = __expf(s[i][j] - mn);
                s[i][j] = p;
                rs += p;
            }
#pragma unroll
            for (int off = 8; off > 0; off >>= 1)
                rs += __shfl_xor_sync(0xffffffffu, rs, off, 16);
            lrow[i] = lrow[i] * alpha + rs;
            mrow[i] = mn;
#pragma unroll
            for (int j = 0; j < 4; j++) O[i][j] *= alpha;
        }

        // Stage P through smem
#pragma unroll
        for (int i = 0; i < 4; i++) {
            float4 pv = make_float4(s[i][0], s[i][1], s[i][2], s[i][3]);
            *(float4*)&Ps[((ty << 2) + i) * SP + (tx << 2)] = pv;
        }
        __syncthreads();

        // O += P @ V
#pragma unroll
        for (int k0 = 0; k0 < 64; k0 += 4) {
            float p[4][4], v[4][4];
#pragma unroll
            for (int i = 0; i < 4; i++)
                *(float4*)&p[i][0] = *(const float4*)&Ps[((ty << 2) + i) * SP + k0];
#pragma unroll
            for (int l = 0; l < 4; l++)
                *(float4*)&v[l][0] = *(const float4*)&Vs[(k0 + l) * SP + (tx << 2)];
#pragma unroll
            for (int i = 0; i < 4; i++)
#pragma unroll
                for (int l = 0; l < 4; l++)
#pragma unroll
                    for (int j = 0; j < 4; j++)
                        O[i][j] += p[i][l] * v[l][j];
        }
    }

    // Normalize and write y in [B, T, H*DH] layout (ready for output GEMM)
#pragma unroll
    for (int i = 0; i < 4; i++) {
        int r = (qb << 6) + (ty << 2) + i;
        float inv = 1.0f / lrow[i];
        float4 o = make_float4(O[i][0] * inv, O[i][1] * inv,
                               O[i][2] * inv, O[i][3] * inv);
        *(float4*)&y[((size_t)b * TT + r) * DIMM + h * DHH + (tx << 2)] = o;
    }
}

// ---------------------------------------------------------------------------
extern "C" void kernel_launch(void* const* d_in, const int* in_sizes, int n_in,
                              void* d_out, int out_size)
{
    const float* x     = (const float*)d_in[0];
    // d_in[1]: mask (int32) — causal structure is known, unused
    const float* W_qkv = (const float*)d_in[2];
    const float* b_qkv = (const float*)d_in[3];
    const float* W_out = (const float*)d_in[4];
    const float* b_out = (const float*)d_in[5];
    float* out = (float*)d_out;

    float *qkv, *y;
    cudaGetSymbolAddress((void**)&qkv, g_qkv);
    cudaGetSymbolAddress((void**)&y, g_y);

    const int attn_smem = 4 * 64 * SP * (int)sizeof(float);  // 69632 B
    cudaFuncSetAttribute(attn_kernel,
                         cudaFuncAttributeMaxDynamicSharedMemorySize, attn_smem);

    dim3 blk(256);

    // 1) qkv = x @ W_qkv + b_qkv      [4096,1024]x[1024,3072]
    sgemm_bias_kernel<<<dim3(QKVN / 128, MROWS / 128), blk>>>(
        x, W_qkv, b_qkv, qkv, MROWS, QKVN, DIMM);

    // 2) RoPE in place on q, k
    rope_kernel<<<(MROWS * HH * 32 + 255) / 256, 256>>>(qkv);

    // 3) causal flash attention -> y  [B,T,DIM]
    attn_kernel<<<dim3(TT / 64, HH, BB), blk, attn_smem>>>(qkv, y);

    // 4) out = y @ W_out + b_out      [4096,1024]x[1024,1024]
    sgemm_bias_kernel<<<dim3(DIMM / 128, MROWS / 128), blk>>>(
        y, W_out, b_out, out, MROWS, DIMM, DIMM);
}

// round 2
// speedup vs baseline: 1.2863x; 1.2863x over previous
#include <cuda_runtime.h>
#include <math.h>

#define BB    2
#define TT    2048
#define DIMM  1024
#define HH    16
#define DHH   64
#define MROWS (BB * TT)        // 4096
#define QKVN  (3 * DIMM)       // 3072
#define SP    68               // sgemm smem pad

// attention tile config
#define BQ   128
#define BK   64
#define QSP  68                // 8-row x 4-col fragment pattern -> stride%32==4
#define KSP  68
#define VSP  72                // 4-row x 8-col fragment pattern -> stride%32==8
#define PSP  68

// Scratch (allocation-free rule: __device__ globals)
__device__ float g_qkv[(size_t)MROWS * QKVN];   // [4096, 3072] q|k|v
__device__ float g_y[(size_t)MROWS * DIMM];     // attention output [4096, 1024]

// ---------------------------------------------------------------------------
// tf32 helpers
// ---------------------------------------------------------------------------
__device__ __forceinline__ float f2tf32(float x) {
    unsigned u;
    asm("cvt.rna.tf32.f32 %0, %1;" : "=r"(u) : "f"(x));
    return __uint_as_float(u);
}

__device__ __forceinline__ void mma_tf32(float* d, const unsigned* a, const unsigned* b) {
    asm("mma.sync.aligned.m16n8k8.row.col.f32.tf32.tf32.f32 "
        "{%0,%1,%2,%3}, {%4,%5,%6,%7}, {%8,%9}, {%0,%1,%2,%3};"
        : "+f"(d[0]), "+f"(d[1]), "+f"(d[2]), "+f"(d[3])
        : "r"(a[0]), "r"(a[1]), "r"(a[2]), "r"(a[3]), "r"(b[0]), "r"(b[1]));
}

// ---------------------------------------------------------------------------
// SGEMM: C[M,N] = A[M,K] @ Bm[K,N] + bias[N]  (unchanged from round 1)
// ---------------------------------------------------------------------------
__global__ __launch_bounds__(256, 2)
void sgemm_bias_kernel(const float* __restrict__ A, const float* __restrict__ Bm,
                       const float* __restrict__ bias, float* __restrict__ C,
                       int M, int N, int K)
{
    __shared__ float As[8][128];
    __shared__ float Bs[8][128];

    const int tid = threadIdx.x;
    const int tx  = tid & 15;
    const int ty  = tid >> 4;
    const int m0  = blockIdx.y * 128;
    const int n0  = blockIdx.x * 128;

    const int arow = tid >> 1;
    const int acol = (tid & 1) << 2;
    const int brow = tid >> 5;
    const int bcol = (tid & 31) << 2;

    float acc[8][8];
#pragma unroll
    for (int i = 0; i < 8; i++)
#pragma unroll
        for (int j = 0; j < 8; j++) acc[i][j] = 0.f;

    const float* Aptr = A + (size_t)(m0 + arow) * K + acol;
    const float* Bptr = Bm + (size_t)brow * N + n0 + bcol;

    float4 av = *(const float4*)Aptr;
    float4 bv = *(const float4*)Bptr;

    const int ntiles = K >> 3;
    for (int kt = 0; kt < ntiles; kt++) {
        As[acol + 0][arow] = av.x;
        As[acol + 1][arow] = av.y;
        As[acol + 2][arow] = av.z;
        As[acol + 3][arow] = av.w;
        *(float4*)&Bs[brow][bcol] = bv;
        __syncthreads();

        if (kt + 1 < ntiles) {
            av = *(const float4*)(Aptr + (size_t)(kt + 1) * 8);
            bv = *(const float4*)(Bptr + (size_t)(kt + 1) * 8 * N);
        }

#pragma unroll
        for (int k = 0; k < 8; k++) {
            float a[8], b[8];
            *(float4*)&a[0] = *(const float4*)&As[k][(ty << 2)];
            *(float4*)&a[4] = *(const float4*)&As[k][64 + (ty << 2)];
            *(float4*)&b[0] = *(const float4*)&Bs[k][(tx << 2)];
            *(float4*)&b[4] = *(const float4*)&Bs[k][64 + (tx << 2)];
#pragma unroll
            for (int i = 0; i < 8; i++)
#pragma unroll
                for (int j = 0; j < 8; j++)
                    acc[i][j] += a[i] * b[j];
        }
        __syncthreads();
    }

#pragma unroll
    for (int ih = 0; ih < 2; ih++) {
#pragma unroll
        for (int i = 0; i < 4; i++) {
            int r = m0 + ih * 64 + (ty << 2) + i;
            float* Crow = C + (size_t)r * N + n0;
#pragma unroll
            for (int jh = 0; jh < 2; jh++) {
                int c = jh * 64 + (tx << 2);
                float4 o;
                o.x = acc[ih * 4 + i][jh * 4 + 0] + bias[n0 + c + 0];
                o.y = acc[ih * 4 + i][jh * 4 + 1] + bias[n0 + c + 1];
                o.z = acc[ih * 4 + i][jh * 4 + 2] + bias[n0 + c + 2];
                o.w = acc[ih * 4 + i][jh * 4 + 3] + bias[n0 + c + 3];
                *(float4*)&Crow[c] = o;
            }
        }
    }
}

// ---------------------------------------------------------------------------
// RoPE in-place on q and k slices (fp64 angles). Unchanged.
// ---------------------------------------------------------------------------
__global__ void rope_kernel(float* __restrict__ qkv)
{
    int idx = blockIdx.x * blockDim.x + threadIdx.x;
    if (idx >= MROWS * HH * 32) return;
    int d = idx & 31;
    int h = (idx >> 5) & (HH - 1);
    int m = idx >> 9;
    int t = m & (TT - 1);

    double inv = pow(10000.0, -(double)d / 32.0);
    double ang = (double)t * inv;
    float c = (float)cos(ang);
    float s = (float)sin(ang);

    float* qp = qkv + (size_t)m * QKVN + h * DHH;
    float a = qp[d], b2 = qp[32 + d];
    qp[d]      = a * c - b2 * s;
    qp[32 + d] = a * s + b2 * c;

    float* kp = qp + DIMM;
    a = kp[d]; b2 = kp[32 + d];
    kp[d]      = a * c - b2 * s;
    kp[32 + d] = a * s + b2 * c;
}

// ---------------------------------------------------------------------------
// Flash attention (causal) with tf32 mma.sync (m16n8k8).
// BQ=128 q rows, BK=64 kv, 8 warps; warp w owns q rows [16w, 16w+16).
// Fragments gathered straight from row-major smem tiles with pad strides
// chosen for conflict-free LDS.
// Dynamic smem: (128*68 + 64*68 + 64*72 + 8*16*68) * 4 = 105472 B
// ---------------------------------------------------------------------------
__global__ __launch_bounds__(256, 2)
void attn_mma_kernel(const float* __restrict__ qkv, float* __restrict__ y)
{
    extern __shared__ float sm[];
    float* Qs = sm;                       // [128][QSP]
    float* Ks = Qs + BQ * QSP;            // [64][KSP]
    float* Vs = Ks + BK * KSP;            // [64][VSP]
    float* Ps = Vs + BK * VSP;            // 8 x [16][PSP]

    const int qb   = gridDim.x - 1 - blockIdx.x;   // heavy CTAs first
    const int h    = blockIdx.y;
    const int b    = blockIdx.z;
    const int tid  = threadIdx.x;
    const int wid  = tid >> 5;
    const int lane = tid & 31;
    const int g    = lane >> 2;          // group (row within fragment)
    const int t    = lane & 3;           // thread-in-group

    const float* base = qkv + (size_t)b * TT * QKVN + h * DHH;

    // ---- stage Q (tf32-rounded) ----
#pragma unroll
    for (int l = 0; l < 8; l++) {
        int idx = tid + l * 256;
        int r   = idx >> 4;
        int c4  = (idx & 15) << 2;
        float4 v = *(const float4*)&base[(size_t)(qb * BQ + r) * QKVN + c4];
        float4 w = make_float4(f2tf32(v.x), f2tf32(v.y), f2tf32(v.z), f2tf32(v.w));
        *(float4*)&Qs[r * QSP + c4] = w;
    }

    float O[8][4];
#pragma unroll
    for (int nf = 0; nf < 8; nf++)
#pragma unroll
        for (int j = 0; j < 4; j++) O[nf][j] = 0.f;
    float m_lo = -1e30f, m_hi = -1e30f, l_lo = 0.f, l_hi = 0.f;

    const int rw0 = qb * BQ + wid * 16;           // warp's first global row
    float* Pw = Ps + wid * 16 * PSP;
    const int nkb = 2 * qb + 2;

    for (int kb = 0; kb < nkb; kb++) {
        __syncthreads();
        // ---- stage K, V (tf32-rounded) ----
#pragma unroll
        for (int l = 0; l < 4; l++) {
            int idx = tid + l * 256;
            int r   = idx >> 4;
            int c4  = (idx & 15) << 2;
            size_t gix = (size_t)(kb * BK + r) * QKVN + c4;
            float4 kv4 = *(const float4*)&base[DIMM + gix];
            float4 kw = make_float4(f2tf32(kv4.x), f2tf32(kv4.y), f2tf32(kv4.z), f2tf32(kv4.w));
            *(float4*)&Ks[r * KSP + c4] = kw;
            float4 vv4 = *(const float4*)&base[2 * DIMM + gix];
            float4 vw = make_float4(f2tf32(vv4.x), f2tf32(vv4.y), f2tf32(vv4.z), f2tf32(vv4.w));
            *(float4*)&Vs[r * VSP + c4] = vw;
        }
        __syncthreads();

        if (kb * BK > rw0 + 15) continue;   // warp tile fully masked

        // ---- S = Q K^T (tf32 mma) ----
        float S[8][4];
#pragma unroll
        for (int nf = 0; nf < 8; nf++)
#pragma unroll
            for (int j = 0; j < 4; j++) S[nf][j] = 0.f;

#pragma unroll
        for (int k0 = 0; k0 < 64; k0 += 8) {
            unsigned a[4];
            a[0] = __float_as_uint(Qs[(wid * 16 + g) * QSP + k0 + t]);
            a[1] = __float_as_uint(Qs[(wid * 16 + g + 8) * QSP + k0 + t]);
            a[2] = __float_as_uint(Qs[(wid * 16 + g) * QSP + k0 + t + 4]);
            a[3] = __float_as_uint(Qs[(wid * 16 + g + 8) * QSP + k0 + t + 4]);
#pragma unroll
            for (int nf = 0; nf < 8; nf++) {
                unsigned bb[2];
                bb[0] = __float_as_uint(Ks[(nf * 8 + g) * KSP + k0 + t]);
                bb[1] = __float_as_uint(Ks[(nf * 8 + g) * KSP + k0 + t + 4]);
                mma_tf32(S[nf], a, bb);
            }
        }

        // ---- scale + causal mask ----
        const int r0 = rw0 + g;
        const int r1 = r0 + 8;
        const bool needmask = (kb * BK + 63 > rw0);
#pragma unroll
        for (int nf = 0; nf < 8; nf++) {
            int c0 = kb * BK + nf * 8 + 2 * t;
            S[nf][0] *= 0.125f; S[nf][1] *= 0.125f;
            S[nf][2] *= 0.125f; S[nf][3] *= 0.125f;
            if (needmask) {
                if (c0     > r0) S[nf][0] = -1e30f;
                if (c0 + 1 > r0) S[nf][1] = -1e30f;
                if (c0     > r1) S[nf][2] = -1e30f;
                if (c0 + 1 > r1) S[nf][3] = -1e30f;
            }
        }

        // ---- online softmax (rows g and g+8, quad-replicated) ----
        float mx0 = -1e30f, mx1 = -1e30f;
#pragma unroll
        for (int nf = 0; nf < 8; nf++) {
            mx0 = fmaxf(mx0, fmaxf(S[nf][0], S[nf][1]));
            mx1 = fmaxf(mx1, fmaxf(S[nf][2], S[nf][3]));
        }
        mx0 = fmaxf(mx0, __shfl_xor_sync(0xffffffffu, mx0, 1));
        mx0 = fmaxf(mx0, __shfl_xor_sync(0xffffffffu, mx0, 2));
        mx1 = fmaxf(mx1, __shfl_xor_sync(0xffffffffu, mx1, 1));
        mx1 = fmaxf(mx1, __shfl_xor_sync(0xffffffffu, mx1, 2));

        float mn0 = fmaxf(m_lo, mx0);
        float mn1 = fmaxf(m_hi, mx1);
        float al0 = __expf(m_lo - mn0);
        float al1 = __expf(m_hi - mn1);
        float rs0 = 0.f, rs1 = 0.f;
#pragma unroll
        for (int nf = 0; nf < 8; nf++) {
            S[nf][0] = __expf(S[nf][0] - mn0);
            S[nf][1] = __expf(S[nf][1] - mn0);
            S[nf][2] = __expf(S[nf][2] - mn1);
            S[nf][3] = __expf(S[nf][3] - mn1);
            rs0 += S[nf][0] + S[nf][1];
            rs1 += S[nf][2] + S[nf][3];
        }
        rs0 += __shfl_xor_sync(0xffffffffu, rs0, 1);
        rs0 += __shfl_xor_sync(0xffffffffu, rs0, 2);
        rs1 += __shfl_xor_sync(0xffffffffu, rs1, 1);
        rs1 += __shfl_xor_sync(0xffffffffu, rs1, 2);
        l_lo = l_lo * al0 + rs0;  m_lo = mn0;
        l_hi = l_hi * al1 + rs1;  m_hi = mn1;
#pragma unroll
        for (int nf = 0; nf < 8; nf++) {
            O[nf][0] *= al0; O[nf][1] *= al0;
            O[nf][2] *= al1; O[nf][3] *= al1;
        }

        // ---- stage P (per-warp region, tf32-rounded) ----
#pragma unroll
        for (int nf = 0; nf < 8; nf++) {
            float2 p0 = make_float2(f2tf32(S[nf][0]), f2tf32(S[nf][1]));
            float2 p1 = make_float2(f2tf32(S[nf][2]), f2tf32(S[nf][3]));
            *(float2*)&Pw[g * PSP + nf * 8 + 2 * t]       = p0;
            *(float2*)&Pw[(g + 8) * PSP + nf * 8 + 2 * t] = p1;
        }
        __syncwarp();

        // ---- O += P @ V ----
#pragma unroll
        for (int k0 = 0; k0 < 64; k0 += 8) {
            unsigned a[4];
            a[0] = __float_as_uint(Pw[g * PSP + k0 + t]);
            a[1] = __float_as_uint(Pw[(g + 8) * PSP + k0 + t]);
            a[2] = __float_as_uint(Pw[g * PSP + k0 + t + 4]);
            a[3] = __float_as_uint(Pw[(g + 8) * PSP + k0 + t + 4]);
#pragma unroll
            for (int nf = 0; nf < 8; nf++) {
                unsigned bb[2];
                bb[0] = __float_as_uint(Vs[(k0 + t) * VSP + nf * 8 + g]);
                bb[1] = __float_as_uint(Vs[(k0 + t + 4) * VSP + nf * 8 + g]);
                mma_tf32(O[nf], a, bb);
            }
        }
    }

    // ---- normalize + write (y layout [B,T,H*DH]) ----
    const float inv0 = 1.0f / l_lo;
    const float inv1 = 1.0f / l_hi;
    const int r0 = rw0 + g;
    const int r1 = r0 + 8;
    float* yr0 = y + ((size_t)b * TT + r0) * DIMM + h * DHH;
    float* yr1 = y + ((size_t)b * TT + r1) * DIMM + h * DHH;
#pragma unroll
    for (int nf = 0; nf < 8; nf++) {
        int c = nf * 8 + 2 * t;
        *(float2*)&yr0[c] = make_float2(O[nf][0] * inv0, O[nf][1] * inv0);
        *(float2*)&yr1[c] = make_float2(O[nf][2] * inv1, O[nf][3] * inv1);
    }
}

// ---------------------------------------------------------------------------
extern "C" void kernel_launch(void* const* d_in, const int* in_sizes, int n_in,
                              void* d_out, int out_size)
{
    const float* x     = (const float*)d_in[0];
    const float* W_qkv = (const float*)d_in[2];
    const float* b_qkv = (const float*)d_in[3];
    const float* W_out = (const float*)d_in[4];
    const float* b_out = (const float*)d_in[5];
    float* out = (float*)d_out;

    float *qkv, *y;
    cudaGetSymbolAddress((void**)&qkv, g_qkv);
    cudaGetSymbolAddress((void**)&y, g_y);

    const int attn_smem = (BQ * QSP + BK * KSP + BK * VSP + 8 * 16 * PSP) * (int)sizeof(float);
    cudaFuncSetAttribute(attn_mma_kernel,
                         cudaFuncAttributeMaxDynamicSharedMemorySize, attn_smem);

    dim3 blk(256);

    // 1) qkv = x @ W_qkv + b_qkv
    sgemm_bias_kernel<<<dim3(QKVN / 128, MROWS / 128), blk>>>(
        x, W_qkv, b_qkv, qkv, MROWS, QKVN, DIMM);

    // 2) RoPE in place
    rope_kernel<<<(MROWS * HH * 32 + 255) / 256, 256>>>(qkv);

    // 3) causal flash attention (tf32 tensor cores)
    attn_mma_kernel<<<dim3(TT / BQ, HH, BB), blk, attn_smem>>>(qkv, y);

    // 4) out = y @ W_out + b_out
    sgemm_bias_kernel<<<dim3(DIMM / 128, MROWS / 128), blk>>>(
        y, W_out, b_out, out, MROWS, DIMM, DIMM);
}

// round 3
// speedup vs baseline: 1.6431x; 1.2774x over previous
#include <cuda_runtime.h>
#include <math.h>

#define BB    2
#define TT    2048
#define DIMM  1024
#define HH    16
#define DHH   64
#define MROWS (BB * TT)        // 4096
#define QKVN  (3 * DIMM)       // 3072

// attention tile config
#define BQ   128
#define BK   64
#define QSP  68
#define KSP  68
#define VSP  72
#define PSP  68

// gemm tile config
#define GASP 20                // As[m][k] stride: 20g+t distinct mod 32
#define GBSP 136               // Bs[k][n] stride: 8t+g distinct mod 32

// Scratch (allocation-free rule: __device__ globals)
__device__ float g_qkv[(size_t)MROWS * QKVN];   // [4096, 3072] q|k|v
__device__ float g_y[(size_t)MROWS * DIMM];     // attention output [4096, 1024]

// ---------------------------------------------------------------------------
// tf32 helpers
// ---------------------------------------------------------------------------
__device__ __forceinline__ float f2tf32(float x) {
    unsigned u;
    asm("cvt.rna.tf32.f32 %0, %1;" : "=r"(u) : "f"(x));
    return __uint_as_float(u);
}

__device__ __forceinline__ void mma_tf32(float* d, const unsigned* a, const unsigned* b) {
    asm("mma.sync.aligned.m16n8k8.row.col.f32.tf32.tf32.f32 "
        "{%0,%1,%2,%3}, {%4,%5,%6,%7}, {%8,%9}, {%0,%1,%2,%3};"
        : "+f"(d[0]), "+f"(d[1]), "+f"(d[2]), "+f"(d[3])
        : "r"(a[0]), "r"(a[1]), "r"(a[2]), "r"(a[3]), "r"(b[0]), "r"(b[1]));
}

// ---------------------------------------------------------------------------
// tf32 tensor-core GEMM: C[M,N] = A[M,K] @ Bm[K,N] + bias[N]
// CTA 128x128, 4 warps (64x64 each), BK=16 (2 mma k-steps), double-buffered.
// Requires M%128==0, N%128==0, K%16==0.
// ---------------------------------------------------------------------------
__global__ __launch_bounds__(128, 2)
void gemm_tf32_bias_kernel(const float* __restrict__ A, const float* __restrict__ Bm,
                           const float* __restrict__ bias, float* __restrict__ C,
                           int M, int N, int K)
{
    __shared__ float As[2][128 * GASP];   // [m][k], tf32-rounded
    __shared__ float Bs[2][16 * GBSP];    // [k][n], tf32-rounded

    const int tid  = threadIdx.x;
    const int wid  = tid >> 5;
    const int lane = tid & 31;
    const int g    = lane >> 2;
    const int t    = lane & 3;
    const int wr   = wid >> 1;            // warp row (64 m)
    const int wc   = wid & 1;             // warp col (64 n)
    const int m0   = blockIdx.y * 128;
    const int n0   = blockIdx.x * 128;

    const float* Ap = A + (size_t)(m0 + tid) * K;
    const int bkk = tid >> 3;             // 0..15
    const int bn0 = (tid & 7) << 2;       // 0..28
    const float* Bp = Bm + (size_t)bkk * N + n0 + bn0;

    float acc[4][8][4];
#pragma unroll
    for (int mi = 0; mi < 4; mi++)
#pragma unroll
        for (int ni = 0; ni < 8; ni++)
#pragma unroll
            for (int j = 0; j < 4; j++) acc[mi][ni][j] = 0.f;

    const int ntiles = K >> 4;
    float4 pa[4], pb[4];

    // prologue: stage 0
#pragma unroll
    for (int c = 0; c < 4; c++) {
        pa[c] = *(const float4*)(Ap + c * 4);
        pb[c] = *(const float4*)(Bp + c * 32);
    }
    {
        float* as = As[0] + tid * GASP;
        float* bs = Bs[0] + bkk * GBSP + bn0;
#pragma unroll
        for (int c = 0; c < 4; c++) {
            *(float4*)(as + c * 4) = make_float4(f2tf32(pa[c].x), f2tf32(pa[c].y),
                                                 f2tf32(pa[c].z), f2tf32(pa[c].w));
            *(float4*)(bs + c * 32) = make_float4(f2tf32(pb[c].x), f2tf32(pb[c].y),
                                                  f2tf32(pb[c].z), f2tf32(pb[c].w));
        }
    }
    __syncthreads();

    for (int kt = 0; kt < ntiles; kt++) {
        const int buf = kt & 1;

        if (kt + 1 < ntiles) {
            const float* Apn = Ap + (size_t)(kt + 1) * 16;
            const float* Bpn = Bp + (size_t)(kt + 1) * 16 * N;
#pragma unroll
            for (int c = 0; c < 4; c++) {
                pa[c] = *(const float4*)(Apn + c * 4);
                pb[c] = *(const float4*)(Bpn + c * 32);
            }
        }

        const float* as = As[buf];
        const float* bs = Bs[buf];
#pragma unroll
        for (int ks = 0; ks < 2; ks++) {
            unsigned a[4][4];
#pragma unroll
            for (int mi = 0; mi < 4; mi++) {
                int r = wr * 64 + mi * 16 + g;
                a[mi][0] = __float_as_uint(as[r * GASP + ks * 8 + t]);
                a[mi][1] = __float_as_uint(as[(r + 8) * GASP + ks * 8 + t]);
                a[mi][2] = __float_as_uint(as[r * GASP + ks * 8 + t + 4]);
                a[mi][3] = __float_as_uint(as[(r + 8) * GASP + ks * 8 + t + 4]);
            }
#pragma unroll
            for (int ni = 0; ni < 8; ni++) {
                unsigned b[2];
                int n = wc * 64 + ni * 8 + g;
                b[0] = __float_as_uint(bs[(ks * 8 + t) * GBSP + n]);
                b[1] = __float_as_uint(bs[(ks * 8 + t + 4) * GBSP + n]);
#pragma unroll
                for (int mi = 0; mi < 4; mi++)
                    mma_tf32(acc[mi][ni], a[mi], b);
            }
        }

        if (kt + 1 < ntiles) {
            float* asn = As[buf ^ 1] + tid * GASP;
            float* bsn = Bs[buf ^ 1] + bkk * GBSP + bn0;
#pragma unroll
            for (int c = 0; c < 4; c++) {
                *(float4*)(asn + c * 4) = make_float4(f2tf32(pa[c].x), f2tf32(pa[c].y),
                                                      f2tf32(pa[c].z), f2tf32(pa[c].w));
                *(float4*)(bsn + c * 32) = make_float4(f2tf32(pb[c].x), f2tf32(pb[c].y),
                                                       f2tf32(pb[c].z), f2tf32(pb[c].w));
            }
        }
        __syncthreads();
    }

    // epilogue: bias + store
#pragma unroll
    for (int mi = 0; mi < 4; mi++) {
        int r0 = m0 + wr * 64 + mi * 16 + g;
#pragma unroll
        for (int ni = 0; ni < 8; ni++) {
            int c = n0 + wc * 64 + ni * 8 + 2 * t;
            float2 bz = *(const float2*)&bias[c];
            *(float2*)&C[(size_t)r0 * N + c] =
                make_float2(acc[mi][ni][0] + bz.x, acc[mi][ni][1] + bz.y);
            *(float2*)&C[(size_t)(r0 + 8) * N + c] =
                make_float2(acc[mi][ni][2] + bz.x, acc[mi][ni][3] + bz.y);
        }
    }
}

// ---------------------------------------------------------------------------
// RoPE in-place on q and k slices (fp64 angles).
// ---------------------------------------------------------------------------
__global__ void rope_kernel(float* __restrict__ qkv)
{
    int idx = blockIdx.x * blockDim.x + threadIdx.x;
    if (idx >= MROWS * HH * 32) return;
    int d = idx & 31;
    int h = (idx >> 5) & (HH - 1);
    int m = idx >> 9;
    int t = m & (TT - 1);

    double inv = pow(10000.0, -(double)d / 32.0);
    double ang = (double)t * inv;
    float c = (float)cos(ang);
    float s = (float)sin(ang);

    float* qp = qkv + (size_t)m * QKVN + h * DHH;
    float a = qp[d], b2 = qp[32 + d];
    qp[d]      = a * c - b2 * s;
    qp[32 + d] = a * s + b2 * c;

    float* kp = qp + DIMM;
    a = kp[d]; b2 = kp[32 + d];
    kp[d]      = a * c - b2 * s;
    kp[32 + d] = a * s + b2 * c;
}

// ---------------------------------------------------------------------------
// Flash attention (causal) with tf32 mma.sync (m16n8k8). Unchanged from R2.
// ---------------------------------------------------------------------------
__global__ __launch_bounds__(256, 2)
void attn_mma_kernel(const float* __restrict__ qkv, float* __restrict__ y)
{
    extern __shared__ float sm[];
    float* Qs = sm;
    float* Ks = Qs + BQ * QSP;
    float* Vs = Ks + BK * KSP;
    float* Ps = Vs + BK * VSP;

    const int qb   = gridDim.x - 1 - blockIdx.x;
    const int h    = blockIdx.y;
    const int b    = blockIdx.z;
    const int tid  = threadIdx.x;
    const int wid  = tid >> 5;
    const int lane = tid & 31;
    const int g    = lane >> 2;
    const int t    = lane & 3;

    const float* base = qkv + (size_t)b * TT * QKVN + h * DHH;

#pragma unroll
    for (int l = 0; l < 8; l++) {
        int idx = tid + l * 256;
        int r   = idx >> 4;
        int c4  = (idx & 15) << 2;
        float4 v = *(const float4*)&base[(size_t)(qb * BQ + r) * QKVN + c4];
        *(float4*)&Qs[r * QSP + c4] =
            make_float4(f2tf32(v.x), f2tf32(v.y), f2tf32(v.z), f2tf32(v.w));
    }

    float O[8][4];
#pragma unroll
    for (int nf = 0; nf < 8; nf++)
#pragma unroll
        for (int j = 0; j < 4; j++) O[nf][j] = 0.f;
    float m_lo = -1e30f, m_hi = -1e30f, l_lo = 0.f, l_hi = 0.f;

    const int rw0 = qb * BQ + wid * 16;
    float* Pw = Ps + wid * 16 * PSP;
    const int nkb = 2 * qb + 2;

    for (int kb = 0; kb < nkb; kb++) {
        __syncthreads();
#pragma unroll
        for (int l = 0; l < 4; l++) {
            int idx = tid + l * 256;
            int r   = idx >> 4;
            int c4  = (idx & 15) << 2;
            size_t gix = (size_t)(kb * BK + r) * QKVN + c4;
            float4 kv4 = *(const float4*)&base[DIMM + gix];
            *(float4*)&Ks[r * KSP + c4] =
                make_float4(f2tf32(kv4.x), f2tf32(kv4.y), f2tf32(kv4.z), f2tf32(kv4.w));
            float4 vv4 = *(const float4*)&base[2 * DIMM + gix];
            *(float4*)&Vs[r * VSP + c4] =
                make_float4(f2tf32(vv4.x), f2tf32(vv4.y), f2tf32(vv4.z), f2tf32(vv4.w));
        }
        __syncthreads();

        if (kb * BK > rw0 + 15) continue;

        float S[8][4];
#pragma unroll
        for (int nf = 0; nf < 8; nf++)
#pragma unroll
            for (int j = 0; j < 4; j++) S[nf][j] = 0.f;

#pragma unroll
        for (int k0 = 0; k0 < 64; k0 += 8) {
            unsigned a[4];
            a[0] = __float_as_uint(Qs[(wid * 16 + g) * QSP + k0 + t]);
            a[1] = __float_as_uint(Qs[(wid * 16 + g + 8) * QSP + k0 + t]);
            a[2] = __float_as_uint(Qs[(wid * 16 + g) * QSP + k0 + t + 4]);
            a[3] = __float_as_uint(Qs[(wid * 16 + g + 8) * QSP + k0 + t + 4]);
#pragma unroll
            for (int nf = 0; nf < 8; nf++) {
                unsigned bb[2];
                bb[0] = __float_as_uint(Ks[(nf * 8 + g) * KSP + k0 + t]);
                bb[1] = __float_as_uint(Ks[(nf * 8 + g) * KSP + k0 + t + 4]);
                mma_tf32(S[nf], a, bb);
            }
        }

        const int r0 = rw0 + g;
        const int r1 = r0 + 8;
        const bool needmask = (kb * BK + 63 > rw0);
#pragma unroll
        for (int nf = 0; nf < 8; nf++) {
            int c0 = kb * BK + nf * 8 + 2 * t;
            S[nf][0] *= 0.125f; S[nf][1] *= 0.125f;
            S[nf][2] *= 0.125f; S[nf][3] *= 0.125f;
            if (needmask) {
                if (c0     > r0) S[nf][0] = -1e30f;
                if (c0 + 1 > r0) S[nf][1] = -1e30f;
                if (c0     > r1) S[nf][2] = -1e30f;
                if (c0 + 1 > r1) S[nf][3] = -1e30f;
            }
        }

        float mx0 = -1e30f, mx1 = -1e30f;
#pragma unroll
        for (int nf = 0; nf < 8; nf++) {
            mx0 = fmaxf(mx0, fmaxf(S[nf][0], S[nf][1]));
            mx1 = fmaxf(mx1, fmaxf(S[nf][2], S[nf][3]));
        }
        mx0 = fmaxf(mx0, __shfl_xor_sync(0xffffffffu, mx0, 1));
        mx0 = fmaxf(mx0, __shfl_xor_sync(0xffffffffu, mx0, 2));
        mx1 = fmaxf(mx1, __shfl_xor_sync(0xffffffffu, mx1, 1));
        mx1 = fmaxf(mx1, __shfl_xor_sync(0xffffffffu, mx1, 2));

        float mn0 = fmaxf(m_lo, mx0);
        float mn1 = fmaxf(m_hi, mx1);
        float al0 = __expf(m_lo - mn0);
        float al1 = __expf(m_hi - mn1);
        float rs0 = 0.f, rs1 = 0.f;
#pragma unroll
        for (int nf = 0; nf < 8; nf++) {
            S[nf][0] = __expf(S[nf][0] - mn0);
            S[nf][1] = __expf(S[nf][1] - mn0);
            S[nf][2] = __expf(S[nf][2] - mn1);
            S[nf][3] = __expf(S[nf][3] - mn1);
            rs0 += S[nf][0] + S[nf][1];
            rs1 += S[nf][2] + S[nf][3];
        }
        rs0 += __shfl_xor_sync(0xffffffffu, rs0, 1);
        rs0 += __shfl_xor_sync(0xffffffffu, rs0, 2);
        rs1 += __shfl_xor_sync(0xffffffffu, rs1, 1);
        rs1 += __shfl_xor_sync(0xffffffffu, rs1, 2);
        l_lo = l_lo * al0 + rs0;  m_lo = mn0;
        l_hi = l_hi * al1 + rs1;  m_hi = mn1;
#pragma unroll
        for (int nf = 0; nf < 8; nf++) {
            O[nf][0] *= al0; O[nf][1] *= al0;
            O[nf][2] *= al1; O[nf][3] *= al1;
        }

#pragma unroll
        for (int nf = 0; nf < 8; nf++) {
            *(float2*)&Pw[g * PSP + nf * 8 + 2 * t] =
                make_float2(f2tf32(S[nf][0]), f2tf32(S[nf][1]));
            *(float2*)&Pw[(g + 8) * PSP + nf * 8 + 2 * t] =
                make_float2(f2tf32(S[nf][2]), f2tf32(S[nf][3]));
        }
        __syncwarp();

#pragma unroll
        for (int k0 = 0; k0 < 64; k0 += 8) {
            unsigned a[4];
            a[0] = __float_as_uint(Pw[g * PSP + k0 + t]);
            a[1] = __float_as_uint(Pw[(g + 8) * PSP + k0 + t]);
            a[2] = __float_as_uint(Pw[g * PSP + k0 + t + 4]);
            a[3] = __float_as_uint(Pw[(g + 8) * PSP + k0 + t + 4]);
#pragma unroll
            for (int nf = 0; nf < 8; nf++) {
                unsigned bb[2];
                bb[0] = __float_as_uint(Vs[(k0 + t) * VSP + nf * 8 + g]);
                bb[1] = __float_as_uint(Vs[(k0 + t + 4) * VSP + nf * 8 + g]);
                mma_tf32(O[nf], a, bb);
            }
        }
    }

    const float inv0 = 1.0f / l_lo;
    const float inv1 = 1.0f / l_hi;
    const int r0 = rw0 + g;
    const int r1 = r0 + 8;
    float* yr0 = y + ((size_t)b * TT + r0) * DIMM + h * DHH;
    float* yr1 = y + ((size_t)b * TT + r1) * DIMM + h * DHH;
#pragma unroll
    for (int nf = 0; nf < 8; nf++) {
        int c = nf * 8 + 2 * t;
        *(float2*)&yr0[c] = make_float2(O[nf][0] * inv0, O[nf][1] * inv0);
        *(float2*)&yr1[c] = make_float2(O[nf][2] * inv1, O[nf][3] * inv1);
    }
}

// ---------------------------------------------------------------------------
extern "C" void kernel_launch(void* const* d_in, const int* in_sizes, int n_in,
                              void* d_out, int out_size)
{
    const float* x     = (const float*)d_in[0];
    const float* W_qkv = (const float*)d_in[2];
    const float* b_qkv = (const float*)d_in[3];
    const float* W_out = (const float*)d_in[4];
    const float* b_out = (const float*)d_in[5];
    float* out = (float*)d_out;

    float *qkv, *y;
    cudaGetSymbolAddress((void**)&qkv, g_qkv);
    cudaGetSymbolAddress((void**)&y, g_y);

    const int attn_smem = (BQ * QSP + BK * KSP + BK * VSP + 8 * 16 * PSP) * (int)sizeof(float);
    cudaFuncSetAttribute(attn_mma_kernel,
                         cudaFuncAttributeMaxDynamicSharedMemorySize, attn_smem);

    // 1) qkv = x @ W_qkv + b_qkv   (tf32 tensor cores)
    gemm_tf32_bias_kernel<<<dim3(QKVN / 128, MROWS / 128), 128>>>(
        x, W_qkv, b_qkv, qkv, MROWS, QKVN, DIMM);

    // 2) RoPE in place
    rope_kernel<<<(MROWS * HH * 32 + 255) / 256, 256>>>(qkv);

    // 3) causal flash attention (tf32 tensor cores)
    attn_mma_kernel<<<dim3(TT / BQ, HH, BB), 256, attn_smem>>>(qkv, y);

    // 4) out = y @ W_out + b_out   (tf32 tensor cores)
    gemm_tf32_bias_kernel<<<dim3(DIMM / 128, MROWS / 128), 128>>>(
        y, W_out, b_out, out, MROWS, DIMM, DIMM);
}

// round 4
// speedup vs baseline: 1.7137x; 1.0430x over previous
#include <cuda_runtime.h>
#include <math.h>

#define BB    2
#define TT    2048
#define DIMM  1024
#define HH    16
#define DHH   64
#define MROWS (BB * TT)        // 4096
#define QKVN  (3 * DIMM)       // 3072

// attention tile config
#define BQ   128
#define BK   64
#define QSP  68
#define KSP  68
#define VSP  72

// gemm tile config
#define GASP 20                // As[m][k] stride: 20g+t distinct mod 32
#define GBSP 136               // Bs[k][n] stride: 8t+g distinct mod 32

// Scratch (allocation-free rule: __device__ globals)
__device__ float g_qkv[(size_t)MROWS * QKVN];   // [4096, 3072] q|k|v
__device__ float g_y[(size_t)MROWS * DIMM];     // attention output [4096, 1024]

// ---------------------------------------------------------------------------
// helpers
// ---------------------------------------------------------------------------
__device__ __forceinline__ float f2tf32(float x) {
    unsigned u;
    asm("cvt.rna.tf32.f32 %0, %1;" : "=r"(u) : "f"(x));
    return __uint_as_float(u);
}

__device__ __forceinline__ void mma_tf32(float* d, const unsigned* a, const unsigned* b) {
    asm("mma.sync.aligned.m16n8k8.row.col.f32.tf32.tf32.f32 "
        "{%0,%1,%2,%3}, {%4,%5,%6,%7}, {%8,%9}, {%0,%1,%2,%3};"
        : "+f"(d[0]), "+f"(d[1]), "+f"(d[2]), "+f"(d[3])
        : "r"(a[0]), "r"(a[1]), "r"(a[2]), "r"(a[3]), "r"(b[0]), "r"(b[1]));
}

__device__ __forceinline__ unsigned smem_u32(const void* p) {
    return (unsigned)__cvta_generic_to_shared(p);
}
#define CP_ASYNC16(dst, src) \
    asm volatile("cp.async.cg.shared.global [%0], [%1], 16;" :: "r"(dst), "l"(src))
#define CP_COMMIT() asm volatile("cp.async.commit_group;")
#define CP_WAIT1()  asm volatile("cp.async.wait_group 1;")
#define CP_WAIT0()  asm volatile("cp.async.wait_group 0;")

// ---------------------------------------------------------------------------
// tf32 tensor-core GEMM: C[M,N] = A[M,K] @ Bm[K,N] + bias[N]
// CTA 128x128, 256 threads, 8 warps (32x64 each), BK=16, double-buffered.
// ---------------------------------------------------------------------------
__global__ __launch_bounds__(256, 2)
void gemm_tf32_bias_kernel(const float* __restrict__ A, const float* __restrict__ Bm,
                           const float* __restrict__ bias, float* __restrict__ C,
                           int M, int N, int K)
{
    __shared__ float As[2][128 * GASP];
    __shared__ float Bs[2][16 * GBSP];

    const int tid  = threadIdx.x;
    const int wid  = tid >> 5;
    const int lane = tid & 31;
    const int g    = lane >> 2;
    const int t    = lane & 3;
    const int wr   = wid >> 1;            // 0..3: 32-row band
    const int wc   = wid & 1;             // 0..1: 64-col band
    const int m0   = blockIdx.y * 128;
    const int n0   = blockIdx.x * 128;

    const int ar = tid >> 1;              // 0..127
    const int ak = (tid & 1) << 3;        // 0 or 8
    const int bk = tid >> 4;              // 0..15
    const int bn = (tid & 15) << 3;       // 0..120

    const float* Ap = A + (size_t)(m0 + ar) * K + ak;
    const float* Bp = Bm + (size_t)bk * N + n0 + bn;

    float acc[2][8][4];
#pragma unroll
    for (int mi = 0; mi < 2; mi++)
#pragma unroll
        for (int ni = 0; ni < 8; ni++)
#pragma unroll
            for (int j = 0; j < 4; j++) acc[mi][ni][j] = 0.f;

    const int ntiles = K >> 4;
    float4 pa0, pa1, pb0, pb1;

    pa0 = *(const float4*)Ap;       pa1 = *(const float4*)(Ap + 4);
    pb0 = *(const float4*)Bp;       pb1 = *(const float4*)(Bp + 4);
    {
        float* as = As[0] + ar * GASP + ak;
        float* bs = Bs[0] + bk * GBSP + bn;
        *(float4*)as       = make_float4(f2tf32(pa0.x), f2tf32(pa0.y), f2tf32(pa0.z), f2tf32(pa0.w));
        *(float4*)(as + 4) = make_float4(f2tf32(pa1.x), f2tf32(pa1.y), f2tf32(pa1.z), f2tf32(pa1.w));
        *(float4*)bs       = make_float4(f2tf32(pb0.x), f2tf32(pb0.y), f2tf32(pb0.z), f2tf32(pb0.w));
        *(float4*)(bs + 4) = make_float4(f2tf32(pb1.x), f2tf32(pb1.y), f2tf32(pb1.z), f2tf32(pb1.w));
    }
    __syncthreads();

    for (int kt = 0; kt < ntiles; kt++) {
        const int buf = kt & 1;

        if (kt + 1 < ntiles) {
            const float* Apn = Ap + (kt + 1) * 16;
            const float* Bpn = Bp + (size_t)(kt + 1) * 16 * N;
            pa0 = *(const float4*)Apn;  pa1 = *(const float4*)(Apn + 4);
            pb0 = *(const float4*)Bpn;  pb1 = *(const float4*)(Bpn + 4);
        }

        const float* as = As[buf];
        const float* bs = Bs[buf];
#pragma unroll
        for (int ks = 0; ks < 2; ks++) {
            unsigned a[2][4];
#pragma unroll
            for (int mi = 0; mi < 2; mi++) {
                int r = wr * 32 + mi * 16 + g;
                a[mi][0] = __float_as_uint(as[r * GASP + ks * 8 + t]);
                a[mi][1] = __float_as_uint(as[(r + 8) * GASP + ks * 8 + t]);
                a[mi][2] = __float_as_uint(as[r * GASP + ks * 8 + t + 4]);
                a[mi][3] = __float_as_uint(as[(r + 8) * GASP + ks * 8 + t + 4]);
            }
#pragma unroll
            for (int ni = 0; ni < 8; ni++) {
                unsigned b[2];
                int n = wc * 64 + ni * 8 + g;
                b[0] = __float_as_uint(bs[(ks * 8 + t) * GBSP + n]);
                b[1] = __float_as_uint(bs[(ks * 8 + t + 4) * GBSP + n]);
#pragma unroll
                for (int mi = 0; mi < 2; mi++)
                    mma_tf32(acc[mi][ni], a[mi], b);
            }
        }

        if (kt + 1 < ntiles) {
            float* asn = As[buf ^ 1] + ar * GASP + ak;
            float* bsn = Bs[buf ^ 1] + bk * GBSP + bn;
            *(float4*)asn       = make_float4(f2tf32(pa0.x), f2tf32(pa0.y), f2tf32(pa0.z), f2tf32(pa0.w));
            *(float4*)(asn + 4) = make_float4(f2tf32(pa1.x), f2tf32(pa1.y), f2tf32(pa1.z), f2tf32(pa1.w));
            *(float4*)bsn       = make_float4(f2tf32(pb0.x), f2tf32(pb0.y), f2tf32(pb0.z), f2tf32(pb0.w));
            *(float4*)(bsn + 4) = make_float4(f2tf32(pb1.x), f2tf32(pb1.y), f2tf32(pb1.z), f2tf32(pb1.w));
        }
        __syncthreads();
    }

    // epilogue: bias + store
#pragma unroll
    for (int mi = 0; mi < 2; mi++) {
        int r0 = m0 + wr * 32 + mi * 16 + g;
#pragma unroll
        for (int ni = 0; ni < 8; ni++) {
            int c = n0 + wc * 64 + ni * 8 + 2 * t;
            float2 bz = *(const float2*)&bias[c];
            *(float2*)&C[(size_t)r0 * N + c] =
                make_float2(acc[mi][ni][0] + bz.x, acc[mi][ni][1] + bz.y);
            *(float2*)&C[(size_t)(r0 + 8) * N + c] =
                make_float2(acc[mi][ni][2] + bz.x, acc[mi][ni][3] + bz.y);
        }
    }
}

// ---------------------------------------------------------------------------
// RoPE in-place on q and k slices (fp64 angles).
// ---------------------------------------------------------------------------
__global__ void rope_kernel(float* __restrict__ qkv)
{
    int idx = blockIdx.x * blockDim.x + threadIdx.x;
    if (idx >= MROWS * HH * 32) return;
    int d = idx & 31;
    int h = (idx >> 5) & (HH - 1);
    int m = idx >> 9;
    int t = m & (TT - 1);

    double inv = pow(10000.0, -(double)d / 32.0);
    double ang = (double)t * inv;
    float c = (float)cos(ang);
    float s = (float)sin(ang);

    float* qp = qkv + (size_t)m * QKVN + h * DHH;
    float a = qp[d], b2 = qp[32 + d];
    qp[d]      = a * c - b2 * s;
    qp[32 + d] = a * s + b2 * c;

    float* kp = qp + DIMM;
    a = kp[d]; b2 = kp[32 + d];
    kp[d]      = a * c - b2 * s;
    kp[32 + d] = a * s + b2 * c;
}

// ---------------------------------------------------------------------------
// Flash attention (causal), tf32 mma, cp.async double-buffered K/V,
// shuffle-based P redistribution (no P smem).
// smem: Q[128][68] + K[2][64][68] + V[2][64][72] = 106496 B -> 2 CTAs/SM.
// ---------------------------------------------------------------------------
__global__ __launch_bounds__(256, 2)
void attn_mma_kernel(const float* __restrict__ qkv, float* __restrict__ y)
{
    extern __shared__ float sm[];
    float* Qs = sm;                          // [128][QSP]
    float* Kd = Qs + BQ * QSP;               // [2][64][KSP] raw fp32
    float* Vd = Kd + 2 * BK * KSP;           // [2][64][VSP] raw fp32

    const int qb   = gridDim.x - 1 - blockIdx.x;   // heavy CTAs first
    const int h    = blockIdx.y;
    const int b    = blockIdx.z;
    const int tid  = threadIdx.x;
    const int wid  = tid >> 5;
    const int lane = tid & 31;
    const int g    = lane >> 2;
    const int t    = lane & 3;

    const float* base = qkv + (size_t)b * TT * QKVN + h * DHH;

    // staging coords (shared by Q load and cp.async issue)
    const int sr  = tid >> 4;                // 0..15
    const int sc4 = (tid & 15) << 2;         // 0,4,..60

    // ---- stage Q (tf32-rounded) ----
#pragma unroll
    for (int l = 0; l < 8; l++) {
        int r = sr + l * 16;
        float4 v = *(const float4*)&base[(size_t)(qb * BQ + r) * QKVN + sc4];
        *(float4*)&Qs[r * QSP + sc4] =
            make_float4(f2tf32(v.x), f2tf32(v.y), f2tf32(v.z), f2tf32(v.w));
    }

    const unsigned kbase[2] = { smem_u32(Kd), smem_u32(Kd + BK * KSP) };
    const unsigned vbase[2] = { smem_u32(Vd), smem_u32(Vd + BK * VSP) };
    const int nkb = 2 * qb + 2;

    // issue kv tile kb into buffer buf
    auto issue_kv = [&](int kb, int buf) {
#pragma unroll
        for (int l = 0; l < 4; l++) {
            int r = sr + l * 16;
            size_t gix = (size_t)(kb * BK + r) * QKVN + sc4;
            CP_ASYNC16(kbase[buf] + (unsigned)(r * KSP + sc4) * 4,
                       base + DIMM + gix);
            CP_ASYNC16(vbase[buf] + (unsigned)(r * VSP + sc4) * 4,
                       base + 2 * DIMM + gix);
        }
        CP_COMMIT();
    };

    issue_kv(0, 0);
    if (nkb > 1) issue_kv(1, 1);

    float O[8][4];
#pragma unroll
    for (int nf = 0; nf < 8; nf++)
#pragma unroll
        for (int j = 0; j < 4; j++) O[nf][j] = 0.f;
    float m_lo = -1e30f, m_hi = -1e30f, l_lo = 0.f, l_hi = 0.f;

    const int rw0 = qb * BQ + wid * 16;            // warp's first global row

    for (int kb = 0; kb < nkb; kb++) {
        const int buf = kb & 1;
        if (kb + 1 < nkb) { CP_WAIT1(); } else { CP_WAIT0(); }
        __syncthreads();

        if (kb * BK <= rw0 + 15) {                 // warp tile not fully masked
            const float* Ks = Kd + buf * BK * KSP;
            const float* Vs = Vd + buf * BK * VSP;

            // ---- S = Q K^T ----
            float S[8][4];
#pragma unroll
            for (int nf = 0; nf < 8; nf++)
#pragma unroll
                for (int j = 0; j < 4; j++) S[nf][j] = 0.f;

#pragma unroll
            for (int k0 = 0; k0 < 64; k0 += 8) {
                unsigned a[4];
                a[0] = __float_as_uint(Qs[(wid * 16 + g) * QSP + k0 + t]);
                a[1] = __float_as_uint(Qs[(wid * 16 + g + 8) * QSP + k0 + t]);
                a[2] = __float_as_uint(Qs[(wid * 16 + g) * QSP + k0 + t + 4]);
                a[3] = __float_as_uint(Qs[(wid * 16 + g + 8) * QSP + k0 + t + 4]);
#pragma unroll
                for (int nf = 0; nf < 8; nf++) {
                    unsigned bb[2];
                    bb[0] = __float_as_uint(f2tf32(Ks[(nf * 8 + g) * KSP + k0 + t]));
                    bb[1] = __float_as_uint(f2tf32(Ks[(nf * 8 + g) * KSP + k0 + t + 4]));
                    mma_tf32(S[nf], a, bb);
                }
            }

            // ---- scale + causal mask ----
            const int r0 = rw0 + g;
            const int r1 = r0 + 8;
            const bool needmask = (kb * BK + 63 > rw0);
#pragma unroll
            for (int nf = 0; nf < 8; nf++) {
                int c0 = kb * BK + nf * 8 + 2 * t;
                S[nf][0] *= 0.125f; S[nf][1] *= 0.125f;
                S[nf][2] *= 0.125f; S[nf][3] *= 0.125f;
                if (needmask) {
                    if (c0     > r0) S[nf][0] = -1e30f;
                    if (c0 + 1 > r0) S[nf][1] = -1e30f;
                    if (c0     > r1) S[nf][2] = -1e30f;
                    if (c0 + 1 > r1) S[nf][3] = -1e30f;
                }
            }

            // ---- online softmax ----
            float mx0 = -1e30f, mx1 = -1e30f;
#pragma unroll
            for (int nf = 0; nf < 8; nf++) {
                mx0 = fmaxf(mx0, fmaxf(S[nf][0], S[nf][1]));
                mx1 = fmaxf(mx1, fmaxf(S[nf][2], S[nf][3]));
            }
            mx0 = fmaxf(mx0, __shfl_xor_sync(0xffffffffu, mx0, 1));
            mx0 = fmaxf(mx0, __shfl_xor_sync(0xffffffffu, mx0, 2));
            mx1 = fmaxf(mx1, __shfl_xor_sync(0xffffffffu, mx1, 1));
            mx1 = fmaxf(mx1, __shfl_xor_sync(0xffffffffu, mx1, 2));

            float mn0 = fmaxf(m_lo, mx0);
            float mn1 = fmaxf(m_hi, mx1);
            float al0 = __expf(m_lo - mn0);
            float al1 = __expf(m_hi - mn1);
            float rs0 = 0.f, rs1 = 0.f;
#pragma unroll
            for (int nf = 0; nf < 8; nf++) {
                S[nf][0] = __expf(S[nf][0] - mn0);
                S[nf][1] = __expf(S[nf][1] - mn0);
                S[nf][2] = __expf(S[nf][2] - mn1);
                S[nf][3] = __expf(S[nf][3] - mn1);
                rs0 += S[nf][0] + S[nf][1];
                rs1 += S[nf][2] + S[nf][3];
            }
            rs0 += __shfl_xor_sync(0xffffffffu, rs0, 1);
            rs0 += __shfl_xor_sync(0xffffffffu, rs0, 2);
            rs1 += __shfl_xor_sync(0xffffffffu, rs1, 1);
            rs1 += __shfl_xor_sync(0xffffffffu, rs1, 2);
            l_lo = l_lo * al0 + rs0;  m_lo = mn0;
            l_hi = l_hi * al1 + rs1;  m_hi = mn1;
#pragma unroll
            for (int nf = 0; nf < 8; nf++) {
                O[nf][0] *= al0; O[nf][1] *= al0;
                O[nf][2] *= al1; O[nf][3] *= al1;
                S[nf][0] = f2tf32(S[nf][0]); S[nf][1] = f2tf32(S[nf][1]);
                S[nf][2] = f2tf32(S[nf][2]); S[nf][3] = f2tf32(S[nf][3]);
            }

            // ---- O += P @ V : P A-frags via intra-quad shuffles ----
            // dest t needs P cols {k0+t, k0+t+4}; owner quad-lane t>>1 (+2),
            // element parity t&1.
            const int srcA = (lane & 28) | (t >> 1);
            const int srcB = srcA + 2;
            const bool odd = (t & 1);
#pragma unroll
            for (int ks = 0; ks < 8; ks++) {
                float x0 = __shfl_sync(0xffffffffu, S[ks][0], srcA);
                float x1 = __shfl_sync(0xffffffffu, S[ks][1], srcA);
                float x2 = __shfl_sync(0xffffffffu, S[ks][2], srcA);
                float x3 = __shfl_sync(0xffffffffu, S[ks][3], srcA);
                float y0 = __shfl_sync(0xffffffffu, S[ks][0], srcB);
                float y1 = __shfl_sync(0xffffffffu, S[ks][1], srcB);
                float y2 = __shfl_sync(0xffffffffu, S[ks][2], srcB);
                float y3 = __shfl_sync(0xffffffffu, S[ks][3], srcB);
                unsigned a[4];
                a[0] = __float_as_uint(odd ? x1 : x0);
                a[1] = __float_as_uint(odd ? x3 : x2);
                a[2] = __float_as_uint(odd ? y1 : y0);
                a[3] = __float_as_uint(odd ? y3 : y2);
                const int k0 = ks * 8;
#pragma unroll
                for (int nf = 0; nf < 8; nf++) {
                    unsigned bb[2];
                    bb[0] = __float_as_uint(f2tf32(Vs[(k0 + t) * VSP + nf * 8 + g]));
                    bb[1] = __float_as_uint(f2tf32(Vs[(k0 + t + 4) * VSP + nf * 8 + g]));
                    mma_tf32(O[nf], a, bb);
                }
            }
        }

        __syncthreads();                           // all done reading buf
        if (kb + 2 < nkb) issue_kv(kb + 2, buf);
    }

    // ---- normalize + write ----
    const float inv0 = 1.0f / l_lo;
    const float inv1 = 1.0f / l_hi;
    const int r0 = rw0 + g;
    const int r1 = r0 + 8;
    float* yr0 = y + ((size_t)b * TT + r0) * DIMM + h * DHH;
    float* yr1 = y + ((size_t)b * TT + r1) * DIMM + h * DHH;
#pragma unroll
    for (int nf = 0; nf < 8; nf++) {
        int c = nf * 8 + 2 * t;
        *(float2*)&yr0[c] = make_float2(O[nf][0] * inv0, O[nf][1] * inv0);
        *(float2*)&yr1[c] = make_float2(O[nf][2] * inv1, O[nf][3] * inv1);
    }
}

// ---------------------------------------------------------------------------
extern "C" void kernel_launch(void* const* d_in, const int* in_sizes, int n_in,
                              void* d_out, int out_size)
{
    const float* x     = (const float*)d_in[0];
    const float* W_qkv = (const float*)d_in[2];
    const float* b_qkv = (const float*)d_in[3];
    const float* W_out = (const float*)d_in[4];
    const float* b_out = (const float*)d_in[5];
    float* out = (float*)d_out;

    float *qkv, *y;
    cudaGetSymbolAddress((void**)&qkv, g_qkv);
    cudaGetSymbolAddress((void**)&y, g_y);

    const int attn_smem = (BQ * QSP + 2 * BK * KSP + 2 * BK * VSP) * (int)sizeof(float);
    cudaFuncSetAttribute(attn_mma_kernel,
                         cudaFuncAttributeMaxDynamicSharedMemorySize, attn_smem);

    // 1) qkv = x @ W_qkv + b_qkv   (tf32 tensor cores)
    gemm_tf32_bias_kernel<<<dim3(QKVN / 128, MROWS / 128), 256>>>(
        x, W_qkv, b_qkv, qkv, MROWS, QKVN, DIMM);

    // 2) RoPE in place
    rope_kernel<<<(MROWS * HH * 32 + 255) / 256, 256>>>(qkv);

    // 3) causal flash attention (tf32 tensor cores, cp.async pipeline)
    attn_mma_kernel<<<dim3(TT / BQ, HH, BB), 256, attn_smem>>>(qkv, y);

    // 4) out = y @ W_out + b_out   (tf32 tensor cores)
    gemm_tf32_bias_kernel<<<dim3(DIMM / 128, MROWS / 128), 256>>>(
        y, W_out, b_out, out, MROWS, DIMM, DIMM);
}

// round 6
// speedup vs baseline: 3.0915x; 1.8040x over previous
#include <cuda_runtime.h>
#include <math.h>

#define BB    2
#define TT    2048
#define DIMM  1024
#define HH    16
#define DHH   64
#define MROWS (BB * TT)        // 4096
#define QKVN  (3 * DIMM)       // 3072

// attention tile config
#define BQ   128
#define BK   64
#define QSP  68
#define KSP  68
#define VSP  72

// gemm tile config
#define GASP 20                // As[m][k] stride: 20g+t distinct mod 32
#define GBSP 136               // Bs[k][n] stride: 8t+g distinct mod 32

// Scratch (allocation-free rule: __device__ globals)
__device__ float  g_qkv[(size_t)MROWS * QKVN];   // [4096, 3072] q|k|v
__device__ float  g_y[(size_t)MROWS * DIMM];     // attention output [4096, 1024]
__device__ float2 g_rope[TT * 32];               // per-(t,d) cos/sin

// ---------------------------------------------------------------------------
// helpers
// ---------------------------------------------------------------------------
__device__ __forceinline__ float f2tf32(float x) {
    unsigned u;
    asm("cvt.rna.tf32.f32 %0, %1;" : "=r"(u) : "f"(x));
    return __uint_as_float(u);
}

__device__ __forceinline__ void mma_tf32(float* d, const unsigned* a, const unsigned* b) {
    asm("mma.sync.aligned.m16n8k8.row.col.f32.tf32.tf32.f32 "
        "{%0,%1,%2,%3}, {%4,%5,%6,%7}, {%8,%9}, {%0,%1,%2,%3};"
        : "+f"(d[0]), "+f"(d[1]), "+f"(d[2]), "+f"(d[3])
        : "r"(a[0]), "r"(a[1]), "r"(a[2]), "r"(a[3]), "r"(b[0]), "r"(b[1]));
}

__device__ __forceinline__ unsigned smem_u32(const void* p) {
    return (unsigned)__cvta_generic_to_shared(p);
}
#define CP_ASYNC16(dst, src) \
    asm volatile("cp.async.cg.shared.global [%0], [%1], 16;" :: "r"(dst), "l"(src))
#define CP_COMMIT() asm volatile("cp.async.commit_group;")
#define CP_WAIT1()  asm volatile("cp.async.wait_group 1;")
#define CP_WAIT0()  asm volatile("cp.async.wait_group 0;")

// ---------------------------------------------------------------------------
// tf32 tensor-core GEMM: C[M,N] = A[M,K] @ Bm[K,N] + bias[N]
// CTA 128x128, 256 threads, 8 warps (32x64 each), BK=16, double-buffered.
// ---------------------------------------------------------------------------
__global__ __launch_bounds__(256, 2)
void gemm_tf32_bias_kernel(const float* __restrict__ A, const float* __restrict__ Bm,
                           const float* __restrict__ bias, float* __restrict__ C,
                           int M, int N, int K)
{
    __shared__ float As[2][128 * GASP];
    __shared__ float Bs[2][16 * GBSP];

    const int tid  = threadIdx.x;
    const int wid  = tid >> 5;
    const int lane = tid & 31;
    const int g    = lane >> 2;
    const int t    = lane & 3;
    const int wr   = wid >> 1;
    const int wc   = wid & 1;
    const int m0   = blockIdx.y * 128;
    const int n0   = blockIdx.x * 128;

    const int ar = tid >> 1;
    const int ak = (tid & 1) << 3;
    const int bk = tid >> 4;
    const int bn = (tid & 15) << 3;

    const float* Ap = A + (size_t)(m0 + ar) * K + ak;
    const float* Bp = Bm + (size_t)bk * N + n0 + bn;

    float acc[2][8][4];
#pragma unroll
    for (int mi = 0; mi < 2; mi++)
#pragma unroll
        for (int ni = 0; ni < 8; ni++)
#pragma unroll
            for (int j = 0; j < 4; j++) acc[mi][ni][j] = 0.f;

    const int ntiles = K >> 4;
    float4 pa0, pa1, pb0, pb1;

    pa0 = *(const float4*)Ap;       pa1 = *(const float4*)(Ap + 4);
    pb0 = *(const float4*)Bp;       pb1 = *(const float4*)(Bp + 4);
    {
        float* as = As[0] + ar * GASP + ak;
        float* bs = Bs[0] + bk * GBSP + bn;
        *(float4*)as       = make_float4(f2tf32(pa0.x), f2tf32(pa0.y), f2tf32(pa0.z), f2tf32(pa0.w));
        *(float4*)(as + 4) = make_float4(f2tf32(pa1.x), f2tf32(pa1.y), f2tf32(pa1.z), f2tf32(pa1.w));
        *(float4*)bs       = make_float4(f2tf32(pb0.x), f2tf32(pb0.y), f2tf32(pb0.z), f2tf32(pb0.w));
        *(float4*)(bs + 4) = make_float4(f2tf32(pb1.x), f2tf32(pb1.y), f2tf32(pb1.z), f2tf32(pb1.w));
    }
    __syncthreads();

    for (int kt = 0; kt < ntiles; kt++) {
        const int buf = kt & 1;

        if (kt + 1 < ntiles) {
            const float* Apn = Ap + (kt + 1) * 16;
            const float* Bpn = Bp + (size_t)(kt + 1) * 16 * N;
            pa0 = *(const float4*)Apn;  pa1 = *(const float4*)(Apn + 4);
            pb0 = *(const float4*)Bpn;  pb1 = *(const float4*)(Bpn + 4);
        }

        const float* as = As[buf];
        const float* bs = Bs[buf];
#pragma unroll
        for (int ks = 0; ks < 2; ks++) {
            unsigned a[2][4];
#pragma unroll
            for (int mi = 0; mi < 2; mi++) {
                int r = wr * 32 + mi * 16 + g;
                a[mi][0] = __float_as_uint(as[r * GASP + ks * 8 + t]);
                a[mi][1] = __float_as_uint(as[(r + 8) * GASP + ks * 8 + t]);
                a[mi][2] = __float_as_uint(as[r * GASP + ks * 8 + t + 4]);
                a[mi][3] = __float_as_uint(as[(r + 8) * GASP + ks * 8 + t + 4]);
            }
#pragma unroll
            for (int ni = 0; ni < 8; ni++) {
                unsigned b[2];
                int n = wc * 64 + ni * 8 + g;
                b[0] = __float_as_uint(bs[(ks * 8 + t) * GBSP + n]);
                b[1] = __float_as_uint(bs[(ks * 8 + t + 4) * GBSP + n]);
#pragma unroll
                for (int mi = 0; mi < 2; mi++)
                    mma_tf32(acc[mi][ni], a[mi], b);
            }
        }

        if (kt + 1 < ntiles) {
            float* asn = As[buf ^ 1] + ar * GASP + ak;
            float* bsn = Bs[buf ^ 1] + bk * GBSP + bn;
            *(float4*)asn       = make_float4(f2tf32(pa0.x), f2tf32(pa0.y), f2tf32(pa0.z), f2tf32(pa0.w));
            *(float4*)(asn + 4) = make_float4(f2tf32(pa1.x), f2tf32(pa1.y), f2tf32(pa1.z), f2tf32(pa1.w));
            *(float4*)bsn       = make_float4(f2tf32(pb0.x), f2tf32(pb0.y), f2tf32(pb0.z), f2tf32(pb0.w));
            *(float4*)(bsn + 4) = make_float4(f2tf32(pb1.x), f2tf32(pb1.y), f2tf32(pb1.z), f2tf32(pb1.w));
        }
        __syncthreads();
    }

#pragma unroll
    for (int mi = 0; mi < 2; mi++) {
        int r0 = m0 + wr * 32 + mi * 16 + g;
#pragma unroll
        for (int ni = 0; ni < 8; ni++) {
            int c = n0 + wc * 64 + ni * 8 + 2 * t;
            float2 bz = *(const float2*)&bias[c];
            *(float2*)&C[(size_t)r0 * N + c] =
                make_float2(acc[mi][ni][0] + bz.x, acc[mi][ni][1] + bz.y);
            *(float2*)&C[(size_t)(r0 + 8) * N + c] =
                make_float2(acc[mi][ni][2] + bz.x, acc[mi][ni][3] + bz.y);
        }
    }
}

// ---------------------------------------------------------------------------
// RoPE cos/sin table: tab[t*32+d] = (cos, sin) of t * 10000^(-d/32).
// inv built from 5 hardcoded constants (10^(-d/8) via binary expansion of d):
// no fp64 pow. Angle in fp64 (2 DMUL), Cody-Waite mod-2pi in fp64 (3 ops),
// then fp32 sincosf on the reduced argument. ~10 fp64 ops/thread.
// ---------------------------------------------------------------------------
__global__ void rope_table_kernel(float2* __restrict__ tab)
{
    int idx = blockIdx.x * blockDim.x + threadIdx.x;
    if (idx >= TT * 32) return;
    int d = idx & 31;
    int t = idx >> 5;

    double inv = 1.0;
    if (d & 1)  inv *= 0.74989420933245582;    // 10^(-1/8)
    if (d & 2)  inv *= 0.56234132519034907;    // 10^(-1/4)
    if (d & 4)  inv *= 0.31622776601683794;    // 10^(-1/2)
    if (d & 8)  inv *= 0.1;                    // 10^(-1)
    if (d & 16) inv *= 0.01;                   // 10^(-2)

    double ang = (double)t * inv;
    double n = rint(ang * 0.15915494309189535);        // 1/(2*pi)
    double r = fma(-n, 6.2831853071795862, ang);       // 2*pi (hi)
    r = fma(-n, 2.4492935982947064e-16, r);            // 2*pi (lo)

    float s, c;
    sincosf((float)r, &s, &c);
    tab[idx] = make_float2(c, s);
}

// ---------------------------------------------------------------------------
// RoPE apply (pure fp32): rotate q,k in place using the table.
// One thread per (row, head, d in [0,32)).
// ---------------------------------------------------------------------------
__global__ void rope_apply_kernel(float* __restrict__ qkv,
                                  const float2* __restrict__ tab)
{
    int idx = blockIdx.x * blockDim.x + threadIdx.x;
    if (idx >= MROWS * HH * 32) return;
    int d = idx & 31;
    int h = (idx >> 5) & (HH - 1);
    int m = idx >> 9;
    int t = m & (TT - 1);

    float2 cs = tab[(t << 5) | d];

    float* qp = qkv + (size_t)m * QKVN + h * DHH;
    float a = qp[d], b2 = qp[32 + d];
    qp[d]      = a * cs.x - b2 * cs.y;
    qp[32 + d] = a * cs.y + b2 * cs.x;

    float* kp = qp + DIMM;
    a = kp[d]; b2 = kp[32 + d];
    kp[d]      = a * cs.x - b2 * cs.y;
    kp[32 + d] = a * cs.y + b2 * cs.x;
}

// ---------------------------------------------------------------------------
// Flash attention (causal), tf32 mma, cp.async double-buffered K/V,
// shuffle-based P redistribution (no P smem). Unchanged from R4.
// ---------------------------------------------------------------------------
__global__ __launch_bounds__(256, 2)
void attn_mma_kernel(const float* __restrict__ qkv, float* __restrict__ y)
{
    extern __shared__ float sm[];
    float* Qs = sm;
    float* Kd = Qs + BQ * QSP;
    float* Vd = Kd + 2 * BK * KSP;

    const int qb   = gridDim.x - 1 - blockIdx.x;
    const int h    = blockIdx.y;
    const int b    = blockIdx.z;
    const int tid  = threadIdx.x;
    const int wid  = tid >> 5;
    const int lane = tid & 31;
    const int g    = lane >> 2;
    const int t    = lane & 3;

    const float* base = qkv + (size_t)b * TT * QKVN + h * DHH;

    const int sr  = tid >> 4;
    const int sc4 = (tid & 15) << 2;

#pragma unroll
    for (int l = 0; l < 8; l++) {
        int r = sr + l * 16;
        float4 v = *(const float4*)&base[(size_t)(qb * BQ + r) * QKVN + sc4];
        *(float4*)&Qs[r * QSP + sc4] =
            make_float4(f2tf32(v.x), f2tf32(v.y), f2tf32(v.z), f2tf32(v.w));
    }

    const unsigned kbase[2] = { smem_u32(Kd), smem_u32(Kd + BK * KSP) };
    const unsigned vbase[2] = { smem_u32(Vd), smem_u32(Vd + BK * VSP) };
    const int nkb = 2 * qb + 2;

    auto issue_kv = [&](int kb, int buf) {
#pragma unroll
        for (int l = 0; l < 4; l++) {
            int r = sr + l * 16;
            size_t gix = (size_t)(kb * BK + r) * QKVN + sc4;
            CP_ASYNC16(kbase[buf] + (unsigned)(r * KSP + sc4) * 4,
                       base + DIMM + gix);
            CP_ASYNC16(vbase[buf] + (unsigned)(r * VSP + sc4) * 4,
                       base + 2 * DIMM + gix);
        }
        CP_COMMIT();
    };

    issue_kv(0, 0);
    if (nkb > 1) issue_kv(1, 1);

    float O[8][4];
#pragma unroll
    for (int nf = 0; nf < 8; nf++)
#pragma unroll
        for (int j = 0; j < 4; j++) O[nf][j] = 0.f;
    float m_lo = -1e30f, m_hi = -1e30f, l_lo = 0.f, l_hi = 0.f;

    const int rw0 = qb * BQ + wid * 16;

    for (int kb = 0; kb < nkb; kb++) {
        const int buf = kb & 1;
        if (kb + 1 < nkb) { CP_WAIT1(); } else { CP_WAIT0(); }
        __syncthreads();

        if (kb * BK <= rw0 + 15) {
            const float* Ks = Kd + buf * BK * KSP;
            const float* Vs = Vd + buf * BK * VSP;

            float S[8][4];
#pragma unroll
            for (int nf = 0; nf < 8; nf++)
#pragma unroll
                for (int j = 0; j < 4; j++) S[nf][j] = 0.f;

#pragma unroll
            for (int k0 = 0; k0 < 64; k0 += 8) {
                unsigned a[4];
                a[0] = __float_as_uint(Qs[(wid * 16 + g) * QSP + k0 + t]);
                a[1] = __float_as_uint(Qs[(wid * 16 + g + 8) * QSP + k0 + t]);
                a[2] = __float_as_uint(Qs[(wid * 16 + g) * QSP + k0 + t + 4]);
                a[3] = __float_as_uint(Qs[(wid * 16 + g + 8) * QSP + k0 + t + 4]);
#pragma unroll
                for (int nf = 0; nf < 8; nf++) {
                    unsigned bb[2];
                    bb[0] = __float_as_uint(f2tf32(Ks[(nf * 8 + g) * KSP + k0 + t]));
                    bb[1] = __float_as_uint(f2tf32(Ks[(nf * 8 + g) * KSP + k0 + t + 4]));
                    mma_tf32(S[nf], a, bb);
                }
            }

            const int r0 = rw0 + g;
            const int r1 = r0 + 8;
            const bool needmask = (kb * BK + 63 > rw0);
#pragma unroll
            for (int nf = 0; nf < 8; nf++) {
                int c0 = kb * BK + nf * 8 + 2 * t;
                S[nf][0] *= 0.125f; S[nf][1] *= 0.125f;
                S[nf][2] *= 0.125f; S[nf][3] *= 0.125f;
                if (needmask) {
                    if (c0     > r0) S[nf][0] = -1e30f;
                    if (c0 + 1 > r0) S[nf][1] = -1e30f;
                    if (c0     > r1) S[nf][2] = -1e30f;
                    if (c0 + 1 > r1) S[nf][3] = -1e30f;
                }
            }

            float mx0 = -1e30f, mx1 = -1e30f;
#pragma unroll
            for (int nf = 0; nf < 8; nf++) {
                mx0 = fmaxf(mx0, fmaxf(S[nf][0], S[nf][1]));
                mx1 = fmaxf(mx1, fmaxf(S[nf][2], S[nf][3]));
            }
            mx0 = fmaxf(mx0, __shfl_xor_sync(0xffffffffu, mx0, 1));
            mx0 = fmaxf(mx0, __shfl_xor_sync(0xffffffffu, mx0, 2));
            mx1 = fmaxf(mx1, __shfl_xor_sync(0xffffffffu, mx1, 1));
            mx1 = fmaxf(mx1, __shfl_xor_sync(0xffffffffu, mx1, 2));

            float mn0 = fmaxf(m_lo, mx0);
            float mn1 = fmaxf(m_hi, mx1);
            float al0 = __expf(m_lo - mn0);
            float al1 = __expf(m_hi - mn1);
            float rs0 = 0.f, rs1 = 0.f;
#pragma unroll
            for (int nf = 0; nf < 8; nf++) {
                S[nf][0] = __expf(S[nf][0] - mn0);
                S[nf][1] = __expf(S[nf][1] - mn0);
                S[nf][2] = __expf(S[nf][2] - mn1);
                S[nf][3] = __expf(S[nf][3] - mn1);
                rs0 += S[nf][0] + S[nf][1];
                rs1 += S[nf][2] + S[nf][3];
            }
            rs0 += __shfl_xor_sync(0xffffffffu, rs0, 1);
            rs0 += __shfl_xor_sync(0xffffffffu, rs0, 2);
            rs1 += __shfl_xor_sync(0xffffffffu, rs1, 1);
            rs1 += __shfl_xor_sync(0xffffffffu, rs1, 2);
            l_lo = l_lo * al0 + rs0;  m_lo = mn0;
            l_hi = l_hi * al1 + rs1;  m_hi = mn1;
#pragma unroll
            for (int nf = 0; nf < 8; nf++) {
                O[nf][0] *= al0; O[nf][1] *= al0;
                O[nf][2] *= al1; O[nf][3] *= al1;
                S[nf][0] = f2tf32(S[nf][0]); S[nf][1] = f2tf32(S[nf][1]);
                S[nf][2] = f2tf32(S[nf][2]); S[nf][3] = f2tf32(S[nf][3]);
            }

            const int srcA = (lane & 28) | (t >> 1);
            const int srcB = srcA + 2;
            const bool odd = (t & 1);
#pragma unroll
            for (int ks = 0; ks < 8; ks++) {
                float x0 = __shfl_sync(0xffffffffu, S[ks][0], srcA);
                float x1 = __shfl_sync(0xffffffffu, S[ks][1], srcA);
                float x2 = __shfl_sync(0xffffffffu, S[ks][2], srcA);
                float x3 = __shfl_sync(0xffffffffu, S[ks][3], srcA);
                float y0 = __shfl_sync(0xffffffffu, S[ks][0], srcB);
                float y1 = __shfl_sync(0xffffffffu, S[ks][1], srcB);
                float y2 = __shfl_sync(0xffffffffu, S[ks][2], srcB);
                float y3 = __shfl_sync(0xffffffffu, S[ks][3], srcB);
                unsigned a[4];
                a[0] = __float_as_uint(odd ? x1 : x0);
                a[1] = __float_as_uint(odd ? x3 : x2);
                a[2] = __float_as_uint(odd ? y1 : y0);
                a[3] = __float_as_uint(odd ? y3 : y2);
                const int k0 = ks * 8;
#pragma unroll
                for (int nf = 0; nf < 8; nf++) {
                    unsigned bb[2];
                    bb[0] = __float_as_uint(f2tf32(Vs[(k0 + t) * VSP + nf * 8 + g]));
                    bb[1] = __float_as_uint(f2tf32(Vs[(k0 + t + 4) * VSP + nf * 8 + g]));
                    mma_tf32(O[nf], a, bb);
                }
            }
        }

        __syncthreads();
        if (kb + 2 < nkb) issue_kv(kb + 2, buf);
    }

    const float inv0 = 1.0f / l_lo;
    const float inv1 = 1.0f / l_hi;
    const int r0 = rw0 + g;
    const int r1 = r0 + 8;
    float* yr0 = y + ((size_t)b * TT + r0) * DIMM + h * DHH;
    float* yr1 = y + ((size_t)b * TT + r1) * DIMM + h * DHH;
#pragma unroll
    for (int nf = 0; nf < 8; nf++) {
        int c = nf * 8 + 2 * t;
        *(float2*)&yr0[c] = make_float2(O[nf][0] * inv0, O[nf][1] * inv0);
        *(float2*)&yr1[c] = make_float2(O[nf][2] * inv1, O[nf][3] * inv1);
    }
}

// ---------------------------------------------------------------------------
extern "C" void kernel_launch(void* const* d_in, const int* in_sizes, int n_in,
                              void* d_out, int out_size)
{
    const float* x     = (const float*)d_in[0];
    const float* W_qkv = (const float*)d_in[2];
    const float* b_qkv = (const float*)d_in[3];
    const float* W_out = (const float*)d_in[4];
    const float* b_out = (const float*)d_in[5];
    float* out = (float*)d_out;

    float *qkv, *y;
    float2* rope;
    cudaGetSymbolAddress((void**)&qkv, g_qkv);
    cudaGetSymbolAddress((void**)&y, g_y);
    cudaGetSymbolAddress((void**)&rope, g_rope);

    const int attn_smem = (BQ * QSP + 2 * BK * KSP + 2 * BK * VSP) * (int)sizeof(float);
    cudaFuncSetAttribute(attn_mma_kernel,
                         cudaFuncAttributeMaxDynamicSharedMemorySize, attn_smem);

    // 0) rope table (cheap; independent of inputs but recomputed each call)
    rope_table_kernel<<<(TT * 32 + 255) / 256, 256>>>(rope);

    // 1) qkv = x @ W_qkv + b_qkv   (tf32 tensor cores)
    gemm_tf32_bias_kernel<<<dim3(QKVN / 128, MROWS / 128), 256>>>(
        x, W_qkv, b_qkv, qkv, MROWS, QKVN, DIMM);

    // 2) RoPE apply (fp32, table-driven)
    rope_apply_kernel<<<(MROWS * HH * 32 + 255) / 256, 256>>>(qkv, rope);

    // 3) causal flash attention (tf32 tensor cores, cp.async pipeline)
    attn_mma_kernel<<<dim3(TT / BQ, HH, BB), 256, attn_smem>>>(qkv, y);

    // 4) out = y @ W_out + b_out   (tf32 tensor cores)
    gemm_tf32_bias_kernel<<<dim3(DIMM / 128, MROWS / 128), 256>>>(
        y, W_out, b_out, out, MROWS, DIMM, DIMM);
}

// round 8
// speedup vs baseline: 3.2958x; 1.0661x over previous
#include <cuda_runtime.h>
#include <math.h>

#define BB    2
#define TT    2048
#define DIMM  1024
#define HH    16
#define DHH   64
#define MROWS (BB * TT)        // 4096
#define QKVN  (3 * DIMM)       // 3072

// attention tile config
#define BQ   128
#define BK   64
#define QSP  68
#define KSP  68
#define VSP  72

// gemm tile config
#define GASP 20                // As[m][k] stride: conflict-free frag loads
#define GBSP 136               // Bs[k][n] stride
#define GSTG (128 * GASP + 16 * GBSP)   // floats per pipeline stage

// Scratch (allocation-free rule: __device__ globals)
__device__ float  g_qkv[(size_t)MROWS * QKVN];   // [4096, 3072] q|k|v (tf32 after rope)
__device__ float  g_y[(size_t)MROWS * DIMM];     // attention out (tf32-rounded)
__device__ float2 g_rope[TT * 32];               // per-(t,d) cos/sin
__device__ float  g_xr[(size_t)MROWS * DIMM];    // x, tf32-rounded
__device__ float  g_wqkv[(size_t)DIMM * QKVN];   // W_qkv, tf32-rounded
__device__ float  g_wout[(size_t)DIMM * DIMM];   // W_out, tf32-rounded

// ---------------------------------------------------------------------------
// helpers
// ---------------------------------------------------------------------------
__device__ __forceinline__ float f2tf32(float x) {
    unsigned u;
    asm("cvt.rna.tf32.f32 %0, %1;" : "=r"(u) : "f"(x));
    return __uint_as_float(u);
}

__device__ __forceinline__ void mma_tf32(float* d, const unsigned* a, const unsigned* b) {
    asm("mma.sync.aligned.m16n8k8.row.col.f32.tf32.tf32.f32 "
        "{%0,%1,%2,%3}, {%4,%5,%6,%7}, {%8,%9}, {%0,%1,%2,%3};"
        : "+f"(d[0]), "+f"(d[1]), "+f"(d[2]), "+f"(d[3])
        : "r"(a[0]), "r"(a[1]), "r"(a[2]), "r"(a[3]), "r"(b[0]), "r"(b[1]));
}

__device__ __forceinline__ unsigned smem_u32(const void* p) {
    return (unsigned)__cvta_generic_to_shared(p);
}
#define CP_ASYNC16(dst, src) \
    asm volatile("cp.async.cg.shared.global [%0], [%1], 16;" :: "r"(dst), "l"(src))
#define CP_COMMIT() asm volatile("cp.async.commit_group;")
#define CP_WAIT1()  asm volatile("cp.async.wait_group 1;")
#define CP_WAIT0()  asm volatile("cp.async.wait_group 0;")

// ---------------------------------------------------------------------------
// Elementwise tf32 rounding pass (float4-vectorized). n must be %4==0.
// ---------------------------------------------------------------------------
__global__ void round_tf32_kernel(const float* __restrict__ in,
                                  float* __restrict__ out, int n4)
{
    int i = blockIdx.x * blockDim.x + threadIdx.x;
    if (i >= n4) return;
    float4 v = ((const float4*)in)[i];
    ((float4*)out)[i] = make_float4(f2tf32(v.x), f2tf32(v.y),
                                    f2tf32(v.z), f2tf32(v.w));
}

// ---------------------------------------------------------------------------
// tf32 GEMM, operands pre-rounded: C = A @ Bm + bias.
// CTA 128x128, 256 thr, 8 warps (32x64), BK=16, cp.async 3-stage ring.
// ---------------------------------------------------------------------------
__global__ __launch_bounds__(256, 2)
void gemm_tf32_bias_kernel(const float* __restrict__ A, const float* __restrict__ Bm,
                           const float* __restrict__ bias, float* __restrict__ C,
                           int M, int N, int K)
{
    extern __shared__ float smg[];

    const int tid  = threadIdx.x;
    const int wid  = tid >> 5;
    const int lane = tid & 31;
    const int g    = lane >> 2;
    const int t    = lane & 3;
    const int wr   = wid >> 1;
    const int wc   = wid & 1;
    const int m0   = blockIdx.y * 128;
    const int n0   = blockIdx.x * 128;

    const int ar = tid >> 1;
    const int ak = (tid & 1) << 3;
    const int bk = tid >> 4;
    const int bn = (tid & 15) << 3;

    const float* Ap = A + (size_t)(m0 + ar) * K + ak;
    const float* Bp = Bm + (size_t)bk * N + n0 + bn;

    const unsigned as_dst = smem_u32(smg) + (unsigned)(ar * GASP + ak) * 4;
    const unsigned bs_dst = smem_u32(smg) + (unsigned)(128 * GASP + bk * GBSP + bn) * 4;

    float acc[2][8][4];
#pragma unroll
    for (int mi = 0; mi < 2; mi++)
#pragma unroll
        for (int ni = 0; ni < 8; ni++)
#pragma unroll
            for (int j = 0; j < 4; j++) acc[mi][ni][j] = 0.f;

    const int ntiles = K >> 4;

    auto issue = [&](int kt) {
        const unsigned off = (unsigned)((kt % 3) * GSTG) * 4;
        const float* Apn = Ap + kt * 16;
        const float* Bpn = Bp + (size_t)kt * 16 * N;
        CP_ASYNC16(as_dst + off,      Apn);
        CP_ASYNC16(as_dst + off + 16, Apn + 4);
        CP_ASYNC16(bs_dst + off,      Bpn);
        CP_ASYNC16(bs_dst + off + 16, Bpn + 4);
        CP_COMMIT();
    };

    issue(0);
    if (ntiles > 1) issue(1);

    for (int kt = 0; kt < ntiles; kt++) {
        if (kt + 1 < ntiles) { CP_WAIT1(); } else { CP_WAIT0(); }
        __syncthreads();
        if (kt + 2 < ntiles) issue(kt + 2);

        const float* as = smg + (kt % 3) * GSTG;
        const float* bs = as + 128 * GASP;
#pragma unroll
        for (int ks = 0; ks < 2; ks++) {
            unsigned a[2][4];
#pragma unroll
            for (int mi = 0; mi < 2; mi++) {
                int r = wr * 32 + mi * 16 + g;
                a[mi][0] = __float_as_uint(as[r * GASP + ks * 8 + t]);
                a[mi][1] = __float_as_uint(as[(r + 8) * GASP + ks * 8 + t]);
                a[mi][2] = __float_as_uint(as[r * GASP + ks * 8 + t + 4]);
                a[mi][3] = __float_as_uint(as[(r + 8) * GASP + ks * 8 + t + 4]);
            }
#pragma unroll
            for (int ni = 0; ni < 8; ni++) {
                unsigned b[2];
                int n = wc * 64 + ni * 8 + g;
                b[0] = __float_as_uint(bs[(ks * 8 + t) * GBSP + n]);
                b[1] = __float_as_uint(bs[(ks * 8 + t + 4) * GBSP + n]);
#pragma unroll
                for (int mi = 0; mi < 2; mi++)
                    mma_tf32(acc[mi][ni], a[mi], b);
            }
        }
    }

    // epilogue: bias + store
#pragma unroll
    for (int mi = 0; mi < 2; mi++) {
        int r0 = m0 + wr * 32 + mi * 16 + g;
#pragma unroll
        for (int ni = 0; ni < 8; ni++) {
            int c = n0 + wc * 64 + ni * 8 + 2 * t;
            float2 bz = *(const float2*)&bias[c];
            *(float2*)&C[(size_t)r0 * N + c] =
                make_float2(acc[mi][ni][0] + bz.x, acc[mi][ni][1] + bz.y);
            *(float2*)&C[(size_t)(r0 + 8) * N + c] =
                make_float2(acc[mi][ni][2] + bz.x, acc[mi][ni][3] + bz.y);
        }
    }
}

// ---------------------------------------------------------------------------
// RoPE cos/sin table (cheap fp64 without pow; fp32 sincos on reduced arg).
// ---------------------------------------------------------------------------
__global__ void rope_table_kernel(float2* __restrict__ tab)
{
    int idx = blockIdx.x * blockDim.x + threadIdx.x;
    if (idx >= TT * 32) return;
    int d = idx & 31;
    int t = idx >> 5;

    double inv = 1.0;
    if (d & 1)  inv *= 0.74989420933245582;    // 10^(-1/8)
    if (d & 2)  inv *= 0.56234132519034907;    // 10^(-1/4)
    if (d & 4)  inv *= 0.31622776601683794;    // 10^(-1/2)
    if (d & 8)  inv *= 0.1;
    if (d & 16) inv *= 0.01;

    double ang = (double)t * inv;
    double n = rint(ang * 0.15915494309189535);
    double r = fma(-n, 6.2831853071795862, ang);
    r = fma(-n, 2.4492935982947064e-16, r);

    float s, c;
    sincosf((float)r, &s, &c);
    tab[idx] = make_float2(c, s);
}

// ---------------------------------------------------------------------------
// RoPE apply + tf32 store: rotate q,k (fp32 math, tf32-rounded store) and
// round v in place. One thread per (row, head, d in [0,32)).
// ---------------------------------------------------------------------------
__global__ void rope_apply_kernel(float* __restrict__ qkv,
                                  const float2* __restrict__ tab)
{
    int idx = blockIdx.x * blockDim.x + threadIdx.x;
    if (idx >= MROWS * HH * 32) return;
    int d = idx & 31;
    int h = (idx >> 5) & (HH - 1);
    int m = idx >> 9;
    int t = m & (TT - 1);

    float2 cs = tab[(t << 5) | d];

    float* qp = qkv + (size_t)m * QKVN + h * DHH;
    float a = qp[d], b2 = qp[32 + d];
    qp[d]      = f2tf32(a * cs.x - b2 * cs.y);
    qp[32 + d] = f2tf32(a * cs.y + b2 * cs.x);

    float* kp = qp + DIMM;
    a = kp[d]; b2 = kp[32 + d];
    kp[d]      = f2tf32(a * cs.x - b2 * cs.y);
    kp[32 + d] = f2tf32(a * cs.y + b2 * cs.x);

    float* vp = qp + 2 * DIMM;
    vp[d]      = f2tf32(vp[d]);
    vp[32 + d] = f2tf32(vp[32 + d]);
}

// ---------------------------------------------------------------------------
// Flash attention (causal), tf32 mma, cp.async double-buffered K/V.
// All operands pre-rounded: NO cvt in inner loops (only P after exp).
// ---------------------------------------------------------------------------
__global__ __launch_bounds__(256, 2)
void attn_mma_kernel(const float* __restrict__ qkv, float* __restrict__ y)
{
    extern __shared__ float sm[];
    float* Qs = sm;
    float* Kd = Qs + BQ * QSP;
    float* Vd = Kd + 2 * BK * KSP;

    const int qb   = gridDim.x - 1 - blockIdx.x;
    const int h    = blockIdx.y;
    const int b    = blockIdx.z;
    const int tid  = threadIdx.x;
    const int wid  = tid >> 5;
    const int lane = tid & 31;
    const int g    = lane >> 2;
    const int t    = lane & 3;

    const float* base = qkv + (size_t)b * TT * QKVN + h * DHH;

    const int sr  = tid >> 4;
    const int sc4 = (tid & 15) << 2;

    // ---- stage Q (already tf32) ----
#pragma unroll
    for (int l = 0; l < 8; l++) {
        int r = sr + l * 16;
        *(float4*)&Qs[r * QSP + sc4] =
            *(const float4*)&base[(size_t)(qb * BQ + r) * QKVN + sc4];
    }

    const unsigned kbase[2] = { smem_u32(Kd), smem_u32(Kd + BK * KSP) };
    const unsigned vbase[2] = { smem_u32(Vd), smem_u32(Vd + BK * VSP) };
    const int nkb = 2 * qb + 2;

    auto issue_kv = [&](int kb, int buf) {
#pragma unroll
        for (int l = 0; l < 4; l++) {
            int r = sr + l * 16;
            size_t gix = (size_t)(kb * BK + r) * QKVN + sc4;
            CP_ASYNC16(kbase[buf] + (unsigned)(r * KSP + sc4) * 4,
                       base + DIMM + gix);
            CP_ASYNC16(vbase[buf] + (unsigned)(r * VSP + sc4) * 4,
                       base + 2 * DIMM + gix);
        }
        CP_COMMIT();
    };

    issue_kv(0, 0);
    if (nkb > 1) issue_kv(1, 1);

    float O[8][4];
#pragma unroll
    for (int nf = 0; nf < 8; nf++)
#pragma unroll
        for (int j = 0; j < 4; j++) O[nf][j] = 0.f;
    float m_lo = -1e30f, m_hi = -1e30f, l_lo = 0.f, l_hi = 0.f;

    const int rw0 = qb * BQ + wid * 16;

    for (int kb = 0; kb < nkb; kb++) {
        const int buf = kb & 1;
        if (kb + 1 < nkb) { CP_WAIT1(); } else { CP_WAIT0(); }
        __syncthreads();

        if (kb * BK <= rw0 + 15) {
            const float* Ks = Kd + buf * BK * KSP;
            const float* Vs = Vd + buf * BK * VSP;

            float S[8][4];
#pragma unroll
            for (int nf = 0; nf < 8; nf++)
#pragma unroll
                for (int j = 0; j < 4; j++) S[nf][j] = 0.f;

#pragma unroll
            for (int k0 = 0; k0 < 64; k0 += 8) {
                unsigned a[4];
                a[0] = __float_as_uint(Qs[(wid * 16 + g) * QSP + k0 + t]);
                a[1] = __float_as_uint(Qs[(wid * 16 + g + 8) * QSP + k0 + t]);
                a[2] = __float_as_uint(Qs[(wid * 16 + g) * QSP + k0 + t + 4]);
                a[3] = __float_as_uint(Qs[(wid * 16 + g + 8) * QSP + k0 + t + 4]);
#pragma unroll
                for (int nf = 0; nf < 8; nf++) {
                    unsigned bb[2];
                    bb[0] = __float_as_uint(Ks[(nf * 8 + g) * KSP + k0 + t]);
                    bb[1] = __float_as_uint(Ks[(nf * 8 + g) * KSP + k0 + t + 4]);
                    mma_tf32(S[nf], a, bb);
                }
            }

            const int r0 = rw0 + g;
            const int r1 = r0 + 8;
            const bool needmask = (kb * BK + 63 > rw0);
#pragma unroll
            for (int nf = 0; nf < 8; nf++) {
                int c0 = kb * BK + nf * 8 + 2 * t;
                S[nf][0] *= 0.125f; S[nf][1] *= 0.125f;
                S[nf][2] *= 0.125f; S[nf][3] *= 0.125f;
                if (needmask) {
                    if (c0     > r0) S[nf][0] = -1e30f;
                    if (c0 + 1 > r0) S[nf][1] = -1e30f;
                    if (c0     > r1) S[nf][2] = -1e30f;
                    if (c0 + 1 > r1) S[nf][3] = -1e30f;
                }
            }

            float mx0 = -1e30f, mx1 = -1e30f;
#pragma unroll
            for (int nf = 0; nf < 8; nf++) {
                mx0 = fmaxf(mx0, fmaxf(S[nf][0], S[nf][1]));
                mx1 = fmaxf(mx1, fmaxf(S[nf][2], S[nf][3]));
            }
            mx0 = fmaxf(mx0, __shfl_xor_sync(0xffffffffu, mx0, 1));
            mx0 = fmaxf(mx0, __shfl_xor_sync(0xffffffffu, mx0, 2));
            mx1 = fmaxf(mx1, __shfl_xor_sync(0xffffffffu, mx1, 1));
            mx1 = fmaxf(mx1, __shfl_xor_sync(0xffffffffu, mx1, 2));

            float mn0 = fmaxf(m_lo, mx0);
            float mn1 = fmaxf(m_hi, mx1);
            float al0 = __expf(m_lo - mn0);
            float al1 = __expf(m_hi - mn1);
            float rs0 = 0.f, rs1 = 0.f;
#pragma unroll
            for (int nf = 0; nf < 8; nf++) {
                S[nf][0] = __expf(S[nf][0] - mn0);
                S[nf][1] = __expf(S[nf][1] - mn0);
                S[nf][2] = __expf(S[nf][2] - mn1);
                S[nf][3] = __expf(S[nf][3] - mn1);
                rs0 += S[nf][0] + S[nf][1];
                rs1 += S[nf][2] + S[nf][3];
            }
            rs0 += __shfl_xor_sync(0xffffffffu, rs0, 1);
            rs0 += __shfl_xor_sync(0xffffffffu, rs0, 2);
            rs1 += __shfl_xor_sync(0xffffffffu, rs1, 1);
            rs1 += __shfl_xor_sync(0xffffffffu, rs1, 2);
            l_lo = l_lo * al0 + rs0;  m_lo = mn0;
            l_hi = l_hi * al1 + rs1;  m_hi = mn1;
#pragma unroll
            for (int nf = 0; nf < 8; nf++) {
                O[nf][0] *= al0; O[nf][1] *= al0;
                O[nf][2] *= al1; O[nf][3] *= al1;
                S[nf][0] = f2tf32(S[nf][0]); S[nf][1] = f2tf32(S[nf][1]);
                S[nf][2] = f2tf32(S[nf][2]); S[nf][3] = f2tf32(S[nf][3]);
            }

            const int srcA = (lane & 28) | (t >> 1);
            const int srcB = srcA + 2;
            const bool odd = (t & 1);
#pragma unroll
            for (int ks = 0; ks < 8; ks++) {
                float x0 = __shfl_sync(0xffffffffu, S[ks][0], srcA);
                float x1 = __shfl_sync(0xffffffffu, S[ks][1], srcA);
                float x2 = __shfl_sync(0xffffffffu, S[ks][2], srcA);
                float x3 = __shfl_sync(0xffffffffu, S[ks][3], srcA);
                float y0 = __shfl_sync(0xffffffffu, S[ks][0], srcB);
                float y1 = __shfl_sync(0xffffffffu, S[ks][1], srcB);
                float y2 = __shfl_sync(0xffffffffu, S[ks][2], srcB);
                float y3 = __shfl_sync(0xffffffffu, S[ks][3], srcB);
                unsigned a[4];
                a[0] = __float_as_uint(odd ? x1 : x0);
                a[1] = __float_as_uint(odd ? x3 : x2);
                a[2] = __float_as_uint(odd ? y1 : y0);
                a[3] = __float_as_uint(odd ? y3 : y2);
                const int k0 = ks * 8;
#pragma unroll
                for (int nf = 0; nf < 8; nf++) {
                    unsigned bb[2];
                    bb[0] = __float_as_uint(Vs[(k0 + t) * VSP + nf * 8 + g]);
                    bb[1] = __float_as_uint(Vs[(k0 + t + 4) * VSP + nf * 8 + g]);
                    mma_tf32(O[nf], a, bb);
                }
            }
        }

        __syncthreads();
        if (kb + 2 < nkb) issue_kv(kb + 2, buf);
    }

    // ---- normalize + write y (tf32-rounded: feeds out-proj GEMM directly) ----
    const float inv0 = 1.0f / l_lo;
    const float inv1 = 1.0f / l_hi;
    const int r0 = rw0 + g;
    const int r1 = r0 + 8;
    float* yr0 = y + ((size_t)b * TT + r0) * DIMM + h * DHH;
    float* yr1 = y + ((size_t)b * TT + r1) * DIMM + h * DHH;
#pragma unroll
    for (int nf = 0; nf < 8; nf++) {
        int c = nf * 8 + 2 * t;
        *(float2*)&yr0[c] = make_float2(f2tf32(O[nf][0] * inv0), f2tf32(O[nf][1] * inv0));
        *(float2*)&yr1[c] = make_float2(f2tf32(O[nf][2] * inv1), f2tf32(O[nf][3] * inv1));
    }
}

// ---------------------------------------------------------------------------
extern "C" void kernel_launch(void* const* d_in, const int* in_sizes, int n_in,
                              void* d_out, int out_size)
{
    const float* x     = (const float*)d_in[0];
    const float* W_qkv = (const float*)d_in[2];
    const float* b_qkv = (const float*)d_in[3];
    const float* W_out = (const float*)d_in[4];
    const float* b_out = (const float*)d_in[5];
    float* out = (float*)d_out;

    float *qkv, *y, *xr, *wqkv, *wout;
    float2* rope;
    cudaGetSymbolAddress((void**)&qkv, g_qkv);
    cudaGetSymbolAddress((void**)&y, g_y);
    cudaGetSymbolAddress((void**)&rope, g_rope);
    cudaGetSymbolAddress((void**)&xr, g_xr);
    cudaGetSymbolAddress((void**)&wqkv, g_wqkv);
    cudaGetSymbolAddress((void**)&wout, g_wout);

    const int attn_smem = (BQ * QSP + 2 * BK * KSP + 2 * BK * VSP) * (int)sizeof(float);
    cudaFuncSetAttribute(attn_mma_kernel,
                         cudaFuncAttributeMaxDynamicSharedMemorySize, attn_smem);
    const int gemm_smem = 3 * GSTG * (int)sizeof(float);   // 56832 B
    cudaFuncSetAttribute(gemm_tf32_bias_kernel,
                         cudaFuncAttributeMaxDynamicSharedMemorySize, gemm_smem);

    // 0) pre-round operands to tf32 + rope table
    round_tf32_kernel<<<(MROWS * DIMM / 4 + 255) / 256, 256>>>(x, xr, MROWS * DIMM / 4);
    round_tf32_kernel<<<(DIMM * QKVN / 4 + 255) / 256, 256>>>(W_qkv, wqkv, DIMM * QKVN / 4);
    round_tf32_kernel<<<(DIMM * DIMM / 4 + 255) / 256, 256>>>(W_out, wout, DIMM * DIMM / 4);
    rope_table_kernel<<<(TT * 32 + 255) / 256, 256>>>(rope);

    // 1) qkv = xr @ wqkv + b_qkv
    gemm_tf32_bias_kernel<<<dim3(QKVN / 128, MROWS / 128), 256, gemm_smem>>>(
        xr, wqkv, b_qkv, qkv, MROWS, QKVN, DIMM);

    // 2) RoPE apply (also rounds q,k,v to tf32 in place)
    rope_apply_kernel<<<(MROWS * HH * 32 + 255) / 256, 256>>>(qkv, rope);

    // 3) causal flash attention
    attn_mma_kernel<<<dim3(TT / BQ, HH, BB), 256, attn_smem>>>(qkv, y);

    // 4) out = y @ wout + b_out
    gemm_tf32_bias_kernel<<<dim3(DIMM / 128, MROWS / 128), 256, gemm_smem>>>(
        y, wout, b_out, out, MROWS, DIMM, DIMM);
}

// round 9
// speedup vs baseline: 6.4789x; 1.9658x over previous
#include <cuda_runtime.h>
#include <cuda_fp16.h>
#include <math.h>

#define BB    2
#define TT    2048
#define DIMM  1024
#define HH    16
#define DHH   64
#define MROWS 4096
#define QKVN  3072

// attention smem stride (halves): 144B rows -> conflict-free ldmatrix & LDS
#define ATSP  72
// gemm smem strides (halves)
#define GASP  40                 // A rows: 80B (16B-aligned, 5 mod 8 swizzle)
#define GBSP  136                // B rows: 272B (17 mod 8)
#define GSTGH (128 * GASP + 32 * GBSP)   // halves per stage (9472 -> 18944 B)

// Scratch (allocation-free rule)
__device__ float  g_qkv[(size_t)MROWS * QKVN];    // fp32 qkv (GEMM out)
__device__ __half g_qkvh[(size_t)MROWS * QKVN];   // fp16 qkv (post-rope)
__device__ __half g_y[(size_t)MROWS * DIMM];      // attention out (fp16)
__device__ __half g_xh[(size_t)MROWS * DIMM];     // x -> fp16
__device__ __half g_wqkvh[(size_t)DIMM * QKVN];   // W_qkv -> fp16
__device__ __half g_wouth[(size_t)DIMM * DIMM];   // W_out -> fp16
__device__ float2 g_rope[TT * 32];

// ---------------------------------------------------------------------------
// primitives
// ---------------------------------------------------------------------------
__device__ __forceinline__ void mma_f16(float* d, const unsigned* a, const unsigned* b) {
    asm volatile("mma.sync.aligned.m16n8k16.row.col.f32.f16.f16.f32 "
        "{%0,%1,%2,%3}, {%4,%5,%6,%7}, {%8,%9}, {%0,%1,%2,%3};"
        : "+f"(d[0]), "+f"(d[1]), "+f"(d[2]), "+f"(d[3])
        : "r"(a[0]), "r"(a[1]), "r"(a[2]), "r"(a[3]), "r"(b[0]), "r"(b[1]));
}
__device__ __forceinline__ void ldsm_x4(unsigned* r, unsigned addr) {
    asm volatile("ldmatrix.sync.aligned.m8n8.x4.shared.b16 {%0,%1,%2,%3}, [%4];"
        : "=r"(r[0]), "=r"(r[1]), "=r"(r[2]), "=r"(r[3]) : "r"(addr));
}
__device__ __forceinline__ void ldsm_x4t(unsigned* r, unsigned addr) {
    asm volatile("ldmatrix.sync.aligned.m8n8.x4.trans.shared.b16 {%0,%1,%2,%3}, [%4];"
        : "=r"(r[0]), "=r"(r[1]), "=r"(r[2]), "=r"(r[3]) : "r"(addr));
}
__device__ __forceinline__ unsigned smem_u32(const void* p) {
    return (unsigned)__cvta_generic_to_shared(p);
}
__device__ __forceinline__ unsigned packh2(float lo, float hi) {
    __half2 h = __float22half2_rn(make_float2(lo, hi));
    return *(unsigned*)&h;
}
#define CP_ASYNC16(dst, src) \
    asm volatile("cp.async.cg.shared.global [%0], [%1], 16;" :: "r"(dst), "l"(src))
#define CP_COMMIT() asm volatile("cp.async.commit_group;")
#define CP_WAIT1()  asm volatile("cp.async.wait_group 1;")
#define CP_WAIT0()  asm volatile("cp.async.wait_group 0;")

// ---------------------------------------------------------------------------
// fp32 -> fp16 conversion pass
// ---------------------------------------------------------------------------
__global__ void f32_to_f16_kernel(const float* __restrict__ in,
                                  __half* __restrict__ out, int n4)
{
    int i = blockIdx.x * blockDim.x + threadIdx.x;
    if (i >= n4) return;
    float4 v = ((const float4*)in)[i];
    __half2* o = (__half2*)out;
    o[2 * i]     = __float22half2_rn(make_float2(v.x, v.y));
    o[2 * i + 1] = __float22half2_rn(make_float2(v.z, v.w));
}

// ---------------------------------------------------------------------------
// fp16 GEMM: C_f32[M,N] = A_h[M,K] @ B_h[K,N] + bias.
// CTA 128x128, 8 warps (32x64), BK=32, cp.async 3-stage, ldmatrix frags.
// ---------------------------------------------------------------------------
__global__ __launch_bounds__(256, 2)
void gemm_f16_bias_kernel(const __half* __restrict__ A, const __half* __restrict__ Bm,
                          const float* __restrict__ bias, float* __restrict__ C,
                          int M, int N, int K)
{
    extern __shared__ __half smg[];

    const int tid  = threadIdx.x;
    const int wid  = tid >> 5;
    const int lane = tid & 31;
    const int g    = lane >> 2;
    const int t    = lane & 3;
    const int wr   = wid >> 1;
    const int wc   = wid & 1;
    const int m0   = blockIdx.y * 128;
    const int n0   = blockIdx.x * 128;

    // staging assignment (16B chunks)
    const int arow = tid >> 2, acol = (tid & 3) << 3;          // + row 64 for l=1
    const int brow = tid >> 4, bcol = (tid & 15) << 3;         // + row 16 for l=1
    const __half* pA0 = A + (size_t)(m0 + arow) * K + acol;
    const __half* pA1 = pA0 + (size_t)64 * K;
    const __half* pB0 = Bm + (size_t)brow * N + n0 + bcol;
    const __half* pB1 = pB0 + (size_t)16 * N;
    const unsigned base = smem_u32(smg);
    const unsigned dA0 = base + (unsigned)(arow * GASP + acol) * 2;
    const unsigned dA1 = dA0 + 64 * GASP * 2;
    const unsigned dB0 = base + (unsigned)(128 * GASP + brow * GBSP + bcol) * 2;
    const unsigned dB1 = dB0 + 16 * GBSP * 2;

    // fragment address bases
    const unsigned aC = base + (unsigned)((wr * 32 + (lane & 15)) * GASP + (lane >> 4) * 8) * 2;
    const unsigned bC = base + (unsigned)(128 * GASP + lane * GBSP + wc * 64) * 2;

    float acc[2][8][4];
#pragma unroll
    for (int mi = 0; mi < 2; mi++)
#pragma unroll
        for (int ni = 0; ni < 8; ni++)
#pragma unroll
            for (int j = 0; j < 4; j++) acc[mi][ni][j] = 0.f;

    const int ntiles = K >> 5;

    auto issue = [&](int kt) {
        const unsigned off = (unsigned)((kt % 3) * GSTGH) * 2;
        CP_ASYNC16(dA0 + off, pA0 + kt * 32);
        CP_ASYNC16(dA1 + off, pA1 + kt * 32);
        CP_ASYNC16(dB0 + off, pB0 + (size_t)kt * 32 * N);
        CP_ASYNC16(dB1 + off, pB1 + (size_t)kt * 32 * N);
        CP_COMMIT();
    };

    issue(0);
    if (ntiles > 1) issue(1);

    for (int kt = 0; kt < ntiles; kt++) {
        if (kt + 1 < ntiles) { CP_WAIT1(); } else { CP_WAIT0(); }
        __syncthreads();
        if (kt + 2 < ntiles) issue(kt + 2);

        const unsigned soff = (unsigned)((kt % 3) * GSTGH) * 2;

        unsigned af[2][2][4];   // [ks][mi]
#pragma unroll
        for (int ks = 0; ks < 2; ks++)
#pragma unroll
            for (int mi = 0; mi < 2; mi++)
                ldsm_x4(af[ks][mi], aC + soff + (unsigned)(mi * 16 * GASP + ks * 16) * 2);

#pragma unroll
        for (int ni = 0; ni < 8; ni++) {
            unsigned bf[4];
            ldsm_x4t(bf, bC + soff + (unsigned)(ni * 8) * 2);
#pragma unroll
            for (int mi = 0; mi < 2; mi++) {
                mma_f16(acc[mi][ni], af[0][mi], bf);
                mma_f16(acc[mi][ni], af[1][mi], bf + 2);
            }
        }
    }

    // epilogue: bias + fp32 store
#pragma unroll
    for (int mi = 0; mi < 2; mi++) {
        int r0 = m0 + wr * 32 + mi * 16 + g;
#pragma unroll
        for (int ni = 0; ni < 8; ni++) {
            int c = n0 + wc * 64 + ni * 8 + 2 * t;
            float2 bz = *(const float2*)&bias[c];
            *(float2*)&C[(size_t)r0 * N + c] =
                make_float2(acc[mi][ni][0] + bz.x, acc[mi][ni][1] + bz.y);
            *(float2*)&C[(size_t)(r0 + 8) * N + c] =
                make_float2(acc[mi][ni][2] + bz.x, acc[mi][ni][3] + bz.y);
        }
    }
}

// ---------------------------------------------------------------------------
// RoPE cos/sin table (no fp64 pow; fp32 sincos on Cody-Waite reduced arg)
// ---------------------------------------------------------------------------
__global__ void rope_table_kernel(float2* __restrict__ tab)
{
    int idx = blockIdx.x * blockDim.x + threadIdx.x;
    if (idx >= TT * 32) return;
    int d = idx & 31;
    int t = idx >> 5;

    double inv = 1.0;
    if (d & 1)  inv *= 0.74989420933245582;
    if (d & 2)  inv *= 0.56234132519034907;
    if (d & 4)  inv *= 0.31622776601683794;
    if (d & 8)  inv *= 0.1;
    if (d & 16) inv *= 0.01;

    double ang = (double)t * inv;
    double n = rint(ang * 0.15915494309189535);
    double r = fma(-n, 6.2831853071795862, ang);
    r = fma(-n, 2.4492935982947064e-16, r);

    float s, c;
    sincosf((float)r, &s, &c);
    tab[idx] = make_float2(c, s);
}

// ---------------------------------------------------------------------------
// RoPE apply: read fp32 qkv, rotate q/k (fp32 math), store fp16 qkvh (q,k,v).
// One rounding per element, same as before.
// ---------------------------------------------------------------------------
__global__ void rope_apply_kernel(const float* __restrict__ qkv,
                                  __half* __restrict__ qkvh,
                                  const float2* __restrict__ tab)
{
    int idx = blockIdx.x * blockDim.x + threadIdx.x;
    if (idx >= MROWS * HH * 32) return;
    int d = idx & 31;
    int h = (idx >> 5) & (HH - 1);
    int m = idx >> 9;
    int t = m & (TT - 1);

    float2 cs = tab[(t << 5) | d];

    const float* qp = qkv + (size_t)m * QKVN + h * DHH;
    __half* qh = qkvh + (size_t)m * QKVN + h * DHH;

    float a = qp[d], b2 = qp[32 + d];
    qh[d]      = __float2half(a * cs.x - b2 * cs.y);
    qh[32 + d] = __float2half(a * cs.y + b2 * cs.x);

    a = qp[DIMM + d]; b2 = qp[DIMM + 32 + d];
    qh[DIMM + d]      = __float2half(a * cs.x - b2 * cs.y);
    qh[DIMM + 32 + d] = __float2half(a * cs.y + b2 * cs.x);

    qh[2 * DIMM + d]      = __float2half(qp[2 * DIMM + d]);
    qh[2 * DIMM + 32 + d] = __float2half(qp[2 * DIMM + 32 + d]);
}

// ---------------------------------------------------------------------------
// Flash attention (causal), fp16 mma m16n8k16, cp.async double-buffered K/V,
// ldmatrix fragments, direct S->P fragment pack (no shuffles, no P smem).
// smem: Q[128][72] + K[2][64][72] + V[2][64][72] halves = 55296 B.
// ---------------------------------------------------------------------------
__global__ __launch_bounds__(256, 2)
void attn_f16_kernel(const __half* __restrict__ qkvh, __half* __restrict__ y)
{
    extern __shared__ __half sma[];
    __half* Qs = sma;                       // [128][ATSP]
    __half* Kd = Qs + 128 * ATSP;           // [2][64][ATSP]
    __half* Vd = Kd + 2 * 64 * ATSP;        // [2][64][ATSP]

    const int qb   = gridDim.x - 1 - blockIdx.x;
    const int h    = blockIdx.y;
    const int b    = blockIdx.z;
    const int tid  = threadIdx.x;
    const int wid  = tid >> 5;
    const int lane = tid & 31;
    const int g    = lane >> 2;
    const int t    = lane & 3;

    const __half* base = qkvh + (size_t)b * TT * QKVN + h * DHH;

    // ---- Q via cp.async (16B chunks: 1024 total) ----
    {
        const unsigned qd = smem_u32(Qs);
        int r0c = tid >> 3, c0 = (tid & 7) << 3;
#pragma unroll
        for (int l = 0; l < 4; l++) {
            int r = r0c + l * 32;
            CP_ASYNC16(qd + (unsigned)(r * ATSP + c0) * 2,
                       base + (size_t)(qb * 128 + r) * QKVN + c0);
        }
    }

    const unsigned kdb = smem_u32(Kd), vdb = smem_u32(Vd);
    const int nkb = 2 * qb + 2;
    const int srr = tid >> 3, src = (tid & 7) << 3;

    auto issue_kv = [&](int kb, int buf) {
        const unsigned boff = (unsigned)(buf * 64 * ATSP) * 2;
#pragma unroll
        for (int l = 0; l < 2; l++) {
            int r = srr + l * 32;
            size_t gix = (size_t)(kb * 64 + r) * QKVN + src;
            unsigned doff = (unsigned)(r * ATSP + src) * 2;
            CP_ASYNC16(kdb + boff + doff, base + DIMM + gix);
            CP_ASYNC16(vdb + boff + doff, base + 2 * DIMM + gix);
        }
        CP_COMMIT();
    };

    issue_kv(0, 0);          // group 0 = Q + kv0
    issue_kv(1, 1);          // group 1 (nkb >= 2 always)

    // fragment address bases (byte addrs)
    const unsigned qfc = smem_u32(Qs) +
        (unsigned)((wid * 16 + (lane & 15)) * ATSP + (lane >> 4) * 8) * 2;
    const unsigned kfc = kdb +
        (unsigned)((((lane >> 4) << 3) + (lane & 7)) * ATSP + ((lane >> 3) & 1) * 8) * 2;
    const unsigned vfc = vdb + (unsigned)(lane * ATSP) * 2;

    float O[8][4];
#pragma unroll
    for (int nf = 0; nf < 8; nf++)
#pragma unroll
        for (int j = 0; j < 4; j++) O[nf][j] = 0.f;
    float m_lo = -1e30f, m_hi = -1e30f, l_lo = 0.f, l_hi = 0.f;

    const int rw0 = qb * 128 + wid * 16;

    for (int kb = 0; kb < nkb; kb++) {
        const int buf = kb & 1;
        if (kb + 1 < nkb) { CP_WAIT1(); } else { CP_WAIT0(); }
        __syncthreads();

        if (kb * 64 <= rw0 + 15) {
            const unsigned boff = (unsigned)(buf * 64 * ATSP) * 2;

            // ---- S = Q K^T ----
            float S[8][4];
#pragma unroll
            for (int nf = 0; nf < 8; nf++)
#pragma unroll
                for (int j = 0; j < 4; j++) S[nf][j] = 0.f;

#pragma unroll
            for (int ks = 0; ks < 4; ks++) {
                unsigned aq[4];
                ldsm_x4(aq, qfc + (unsigned)(ks * 16) * 2);
#pragma unroll
                for (int nfp = 0; nfp < 4; nfp++) {
                    unsigned bk[4];
                    ldsm_x4(bk, kfc + boff +
                            (unsigned)(nfp * 16 * ATSP + ks * 16) * 2);
                    mma_f16(S[2 * nfp],     aq, bk);
                    mma_f16(S[2 * nfp + 1], aq, bk + 2);
                }
            }

            // ---- scale + causal mask ----
            const int r0 = rw0 + g;
            const int r1 = r0 + 8;
            const bool needmask = (kb * 64 + 63 > rw0);
#pragma unroll
            for (int nf = 0; nf < 8; nf++) {
                int c0 = kb * 64 + nf * 8 + 2 * t;
                S[nf][0] *= 0.125f; S[nf][1] *= 0.125f;
                S[nf][2] *= 0.125f; S[nf][3] *= 0.125f;
                if (needmask) {
                    if (c0     > r0) S[nf][0] = -1e30f;
                    if (c0 + 1 > r0) S[nf][1] = -1e30f;
                    if (c0     > r1) S[nf][2] = -1e30f;
                    if (c0 + 1 > r1) S[nf][3] = -1e30f;
                }
            }

            // ---- online softmax ----
            float mx0 = -1e30f, mx1 = -1e30f;
#pragma unroll
            for (int nf = 0; nf < 8; nf++) {
                mx0 = fmaxf(mx0, fmaxf(S[nf][0], S[nf][1]));
                mx1 = fmaxf(mx1, fmaxf(S[nf][2], S[nf][3]));
            }
            mx0 = fmaxf(mx0, __shfl_xor_sync(0xffffffffu, mx0, 1));
            mx0 = fmaxf(mx0, __shfl_xor_sync(0xffffffffu, mx0, 2));
            mx1 = fmaxf(mx1, __shfl_xor_sync(0xffffffffu, mx1, 1));
            mx1 = fmaxf(mx1, __shfl_xor_sync(0xffffffffu, mx1, 2));

            float mn0 = fmaxf(m_lo, mx0);
            float mn1 = fmaxf(m_hi, mx1);
            float al0 = __expf(m_lo - mn0);
            float al1 = __expf(m_hi - mn1);
            float rs0 = 0.f, rs1 = 0.f;
#pragma unroll
            for (int nf = 0; nf < 8; nf++) {
                S[nf][0] = __expf(S[nf][0] - mn0);
                S[nf][1] = __expf(S[nf][1] - mn0);
                S[nf][2] = __expf(S[nf][2] - mn1);
                S[nf][3] = __expf(S[nf][3] - mn1);
                rs0 += S[nf][0] + S[nf][1];
                rs1 += S[nf][2] + S[nf][3];
            }
            rs0 += __shfl_xor_sync(0xffffffffu, rs0, 1);
            rs0 += __shfl_xor_sync(0xffffffffu, rs0, 2);
            rs1 += __shfl_xor_sync(0xffffffffu, rs1, 1);
            rs1 += __shfl_xor_sync(0xffffffffu, rs1, 2);
            l_lo = l_lo * al0 + rs0;  m_lo = mn0;
            l_hi = l_hi * al1 + rs1;  m_hi = mn1;
#pragma unroll
            for (int nf = 0; nf < 8; nf++) {
                O[nf][0] *= al0; O[nf][1] *= al0;
                O[nf][2] *= al1; O[nf][3] *= al1;
            }

            // ---- S C-frag -> P A-frag (direct pack, zero shuffles) ----
            unsigned aP[4][4];
#pragma unroll
            for (int ks = 0; ks < 4; ks++) {
                aP[ks][0] = packh2(S[2 * ks][0],     S[2 * ks][1]);
                aP[ks][1] = packh2(S[2 * ks][2],     S[2 * ks][3]);
                aP[ks][2] = packh2(S[2 * ks + 1][0], S[2 * ks + 1][1]);
                aP[ks][3] = packh2(S[2 * ks + 1][2], S[2 * ks + 1][3]);
            }

            // ---- O += P @ V ----
#pragma unroll
            for (int nf = 0; nf < 8; nf++) {
                unsigned vf[8];
                ldsm_x4t(vf,     vfc + boff + (unsigned)(nf * 8) * 2);
                ldsm_x4t(vf + 4, vfc + boff + (unsigned)(32 * ATSP + nf * 8) * 2);
#pragma unroll
                for (int ks = 0; ks < 4; ks++)
                    mma_f16(O[nf], aP[ks], vf + ((ks & 1) * 2) + ((ks >> 1) * 4));
            }
        }

        __syncthreads();
        if (kb + 2 < nkb) issue_kv(kb + 2, buf);
    }

    // ---- normalize + write y (fp16, one rounding) ----
    const float inv0 = 1.0f / l_lo;
    const float inv1 = 1.0f / l_hi;
    const int r0 = rw0 + g;
    const int r1 = r0 + 8;
    __half* yr0 = y + ((size_t)b * TT + r0) * DIMM + h * DHH;
    __half* yr1 = y + ((size_t)b * TT + r1) * DIMM + h * DHH;
#pragma unroll
    for (int nf = 0; nf < 8; nf++) {
        int c = nf * 8 + 2 * t;
        *(unsigned*)&yr0[c] = packh2(O[nf][0] * inv0, O[nf][1] * inv0);
        *(unsigned*)&yr1[c] = packh2(O[nf][2] * inv1, O[nf][3] * inv1);
    }
}

// ---------------------------------------------------------------------------
extern "C" void kernel_launch(void* const* d_in, const int* in_sizes, int n_in,
                              void* d_out, int out_size)
{
    const float* x     = (const float*)d_in[0];
    const float* W_qkv = (const float*)d_in[2];
    const float* b_qkv = (const float*)d_in[3];
    const float* W_out = (const float*)d_in[4];
    const float* b_out = (const float*)d_in[5];
    float* out = (float*)d_out;

    float* qkv;  float2* rope;
    __half *qkvh, *y, *xh, *wqkvh, *wouth;
    cudaGetSymbolAddress((void**)&qkv, g_qkv);
    cudaGetSymbolAddress((void**)&qkvh, g_qkvh);
    cudaGetSymbolAddress((void**)&y, g_y);
    cudaGetSymbolAddress((void**)&xh, g_xh);
    cudaGetSymbolAddress((void**)&wqkvh, g_wqkvh);
    cudaGetSymbolAddress((void**)&wouth, g_wouth);
    cudaGetSymbolAddress((void**)&rope, g_rope);

    const int gemm_smem = 3 * GSTGH * 2;                 // 56832 B
    cudaFuncSetAttribute(gemm_f16_bias_kernel,
                         cudaFuncAttributeMaxDynamicSharedMemorySize, gemm_smem);
    const int attn_smem = (128 + 4 * 64) * ATSP * 2;     // 55296 B
    cudaFuncSetAttribute(attn_f16_kernel,
                         cudaFuncAttributeMaxDynamicSharedMemorySize, attn_smem);

    // 0) convert operands to fp16 + rope table
    f32_to_f16_kernel<<<(MROWS * DIMM / 4 + 255) / 256, 256>>>(x, xh, MROWS * DIMM / 4);
    f32_to_f16_kernel<<<(DIMM * QKVN / 4 + 255) / 256, 256>>>(W_qkv, wqkvh, DIMM * QKVN / 4);
    f32_to_f16_kernel<<<(DIMM * DIMM / 4 + 255) / 256, 256>>>(W_out, wouth, DIMM * DIMM / 4);
    rope_table_kernel<<<(TT * 32 + 255) / 256, 256>>>(rope);

    // 1) qkv = xh @ wqkvh + b_qkv (fp32 out)
    gemm_f16_bias_kernel<<<dim3(QKVN / 128, MROWS / 128), 256, gemm_smem>>>(
        xh, wqkvh, b_qkv, qkv, MROWS, QKVN, DIMM);

    // 2) rope: fp32 qkv -> fp16 qkvh (q,k rotated; v converted)
    rope_apply_kernel<<<(MROWS * HH * 32 + 255) / 256, 256>>>(qkv, qkvh, rope);

    // 3) causal flash attention (fp16 tensor cores) -> y fp16
    attn_f16_kernel<<<dim3(TT / 128, HH, BB), 256, attn_smem>>>(qkvh, y);

    // 4) out = y @ wouth + b_out (fp32 out)
    gemm_f16_bias_kernel<<<dim3(DIMM / 128, MROWS / 128), 256, gemm_smem>>>(
        y, wouth, b_out, out, MROWS, DIMM, DIMM);
}

// round 10
// speedup vs baseline: 7.0554x; 1.0890x over previous
#include <cuda_runtime.h>
#include <cuda_fp16.h>
#include <math.h>

#define BB    2
#define TT    2048
#define DIMM  1024
#define HH    16
#define DHH   64
#define MROWS 4096
#define QKVN  3072

// attention smem stride (halves)
#define ATSP  72
// gemm smem strides (halves)
#define GASP  40
#define GBSP  136
#define GSTGH (128 * GASP + 32 * GBSP)

// Scratch (allocation-free rule)
__device__ __half g_qkvh[(size_t)MROWS * QKVN];   // fp16 qkv (rope fused in GEMM)
__device__ __half g_y[(size_t)MROWS * DIMM];      // attention out (fp16)
__device__ __half g_xh[(size_t)MROWS * DIMM];     // x -> fp16
__device__ __half g_wqkvh[(size_t)DIMM * QKVN];   // W_qkv -> fp16
__device__ __half g_wouth[(size_t)DIMM * DIMM];   // W_out -> fp16
__device__ float2 g_rope[TT * 32];

// ---------------------------------------------------------------------------
// primitives
// ---------------------------------------------------------------------------
__device__ __forceinline__ void mma_f16(float* d, const unsigned* a, const unsigned* b) {
    asm volatile("mma.sync.aligned.m16n8k16.row.col.f32.f16.f16.f32 "
        "{%0,%1,%2,%3}, {%4,%5,%6,%7}, {%8,%9}, {%0,%1,%2,%3};"
        : "+f"(d[0]), "+f"(d[1]), "+f"(d[2]), "+f"(d[3])
        : "r"(a[0]), "r"(a[1]), "r"(a[2]), "r"(a[3]), "r"(b[0]), "r"(b[1]));
}
__device__ __forceinline__ void ldsm_x4(unsigned* r, unsigned addr) {
    asm volatile("ldmatrix.sync.aligned.m8n8.x4.shared.b16 {%0,%1,%2,%3}, [%4];"
        : "=r"(r[0]), "=r"(r[1]), "=r"(r[2]), "=r"(r[3]) : "r"(addr));
}
__device__ __forceinline__ void ldsm_x4t(unsigned* r, unsigned addr) {
    asm volatile("ldmatrix.sync.aligned.m8n8.x4.trans.shared.b16 {%0,%1,%2,%3}, [%4];"
        : "=r"(r[0]), "=r"(r[1]), "=r"(r[2]), "=r"(r[3]) : "r"(addr));
}
__device__ __forceinline__ unsigned smem_u32(const void* p) {
    return (unsigned)__cvta_generic_to_shared(p);
}
__device__ __forceinline__ unsigned packh2(float lo, float hi) {
    __half2 h = __float22half2_rn(make_float2(lo, hi));
    return *(unsigned*)&h;
}
#define CP_ASYNC16(dst, src) \
    asm volatile("cp.async.cg.shared.global [%0], [%1], 16;" :: "r"(dst), "l"(src))
#define CP_COMMIT() asm volatile("cp.async.commit_group;")
#define CP_WAIT1()  asm volatile("cp.async.wait_group 1;")
#define CP_WAIT0()  asm volatile("cp.async.wait_group 0;")

// ---------------------------------------------------------------------------
// Fused fp32 -> fp16 conversion for x, W_qkv, W_out (single launch)
// ---------------------------------------------------------------------------
#define NX4  (MROWS * DIMM / 4)
#define NW14 (DIMM * QKVN / 4)
#define NW24 (DIMM * DIMM / 4)
__global__ void convert_all_kernel(const float* __restrict__ x, __half* __restrict__ xh,
                                   const float* __restrict__ w1, __half* __restrict__ w1h,
                                   const float* __restrict__ w2, __half* __restrict__ w2h)
{
    int i = blockIdx.x * blockDim.x + threadIdx.x;
    const float* in; __half* out; int j;
    if (i < NX4)              { in = x;  out = xh;  j = i; }
    else if (i < NX4 + NW14)  { in = w1; out = w1h; j = i - NX4; }
    else if (i < NX4 + NW14 + NW24) { in = w2; out = w2h; j = i - NX4 - NW14; }
    else return;
    float4 v = ((const float4*)in)[j];
    __half2* o = (__half2*)out;
    o[2 * j]     = __float22half2_rn(make_float2(v.x, v.y));
    o[2 * j + 1] = __float22half2_rn(make_float2(v.z, v.w));
}

// ---------------------------------------------------------------------------
// RoPE cos/sin table (no fp64 pow; fp32 sincos on Cody-Waite reduced arg)
// ---------------------------------------------------------------------------
__global__ void rope_table_kernel(float2* __restrict__ tab)
{
    int idx = blockIdx.x * blockDim.x + threadIdx.x;
    if (idx >= TT * 32) return;
    int d = idx & 31;
    int t = idx >> 5;

    double inv = 1.0;
    if (d & 1)  inv *= 0.74989420933245582;
    if (d & 2)  inv *= 0.56234132519034907;
    if (d & 4)  inv *= 0.31622776601683794;
    if (d & 8)  inv *= 0.1;
    if (d & 16) inv *= 0.01;

    double ang = (double)t * inv;
    double n = rint(ang * 0.15915494309189535);
    double r = fma(-n, 6.2831853071795862, ang);
    r = fma(-n, 2.4492935982947064e-16, r);

    float s, c;
    sincosf((float)r, &s, &c);
    tab[idx] = make_float2(c, s);
}

// ---------------------------------------------------------------------------
// fp16 GEMM, templated epilogue:
//   MODE 0: C32 = A@B + bias (fp32 out)                      [out projection]
//   MODE 1: C16 = rope(A@B + bias) as fp16; q scaled by 1/8  [QKV projection]
// CTA 128x128, 8 warps (32x64), BK=32, cp.async 3-stage, ldmatrix frags.
// MODE 1 relies on: warp 64-col band == one head's 64 dims; rotation pair
// (d', d'+32) lives in fragments ni and ni+4 of the SAME thread.
// ---------------------------------------------------------------------------
template <int MODE>
__global__ __launch_bounds__(256, 2)
void gemm_f16_kernel(const __half* __restrict__ A, const __half* __restrict__ Bm,
                     const float* __restrict__ bias, float* __restrict__ C32,
                     __half* __restrict__ C16, const float2* __restrict__ tab,
                     int M, int N, int K)
{
    extern __shared__ __half smg[];

    const int tid  = threadIdx.x;
    const int wid  = tid >> 5;
    const int lane = tid & 31;
    const int g    = lane >> 2;
    const int t    = lane & 3;
    const int wr   = wid >> 1;
    const int wc   = wid & 1;
    const int m0   = blockIdx.y * 128;
    const int n0   = blockIdx.x * 128;

    const int arow = tid >> 2, acol = (tid & 3) << 3;
    const int brow = tid >> 4, bcol = (tid & 15) << 3;
    const __half* pA0 = A + (size_t)(m0 + arow) * K + acol;
    const __half* pA1 = pA0 + (size_t)64 * K;
    const __half* pB0 = Bm + (size_t)brow * N + n0 + bcol;
    const __half* pB1 = pB0 + (size_t)16 * N;
    const unsigned base = smem_u32(smg);
    const unsigned dA0 = base + (unsigned)(arow * GASP + acol) * 2;
    const unsigned dA1 = dA0 + 64 * GASP * 2;
    const unsigned dB0 = base + (unsigned)(128 * GASP + brow * GBSP + bcol) * 2;
    const unsigned dB1 = dB0 + 16 * GBSP * 2;

    const unsigned aC = base + (unsigned)((wr * 32 + (lane & 15)) * GASP + (lane >> 4) * 8) * 2;
    const unsigned bC = base + (unsigned)(128 * GASP + lane * GBSP + wc * 64) * 2;

    float acc[2][8][4];
#pragma unroll
    for (int mi = 0; mi < 2; mi++)
#pragma unroll
        for (int ni = 0; ni < 8; ni++)
#pragma unroll
            for (int j = 0; j < 4; j++) acc[mi][ni][j] = 0.f;

    const int ntiles = K >> 5;

    auto issue = [&](int kt) {
        const unsigned off = (unsigned)((kt % 3) * GSTGH) * 2;
        CP_ASYNC16(dA0 + off, pA0 + kt * 32);
        CP_ASYNC16(dA1 + off, pA1 + kt * 32);
        CP_ASYNC16(dB0 + off, pB0 + (size_t)kt * 32 * N);
        CP_ASYNC16(dB1 + off, pB1 + (size_t)kt * 32 * N);
        CP_COMMIT();
    };

    issue(0);
    if (ntiles > 1) issue(1);

    for (int kt = 0; kt < ntiles; kt++) {
        if (kt + 1 < ntiles) { CP_WAIT1(); } else { CP_WAIT0(); }
        __syncthreads();
        if (kt + 2 < ntiles) issue(kt + 2);

        const unsigned soff = (unsigned)((kt % 3) * GSTGH) * 2;

        unsigned af[2][2][4];
#pragma unroll
        for (int ks = 0; ks < 2; ks++)
#pragma unroll
            for (int mi = 0; mi < 2; mi++)
                ldsm_x4(af[ks][mi], aC + soff + (unsigned)(mi * 16 * GASP + ks * 16) * 2);

#pragma unroll
        for (int ni = 0; ni < 8; ni++) {
            unsigned bf[4];
            ldsm_x4t(bf, bC + soff + (unsigned)(ni * 8) * 2);
#pragma unroll
            for (int mi = 0; mi < 2; mi++) {
                mma_f16(acc[mi][ni], af[0][mi], bf);
                mma_f16(acc[mi][ni], af[1][mi], bf + 2);
            }
        }
    }

    if (MODE == 0) {
        // fp32 + bias epilogue
#pragma unroll
        for (int mi = 0; mi < 2; mi++) {
            int r0 = m0 + wr * 32 + mi * 16 + g;
#pragma unroll
            for (int ni = 0; ni < 8; ni++) {
                int c = n0 + wc * 64 + ni * 8 + 2 * t;
                float2 bz = *(const float2*)&bias[c];
                *(float2*)&C32[(size_t)r0 * N + c] =
                    make_float2(acc[mi][ni][0] + bz.x, acc[mi][ni][1] + bz.y);
                *(float2*)&C32[(size_t)(r0 + 8) * N + c] =
                    make_float2(acc[mi][ni][2] + bz.x, acc[mi][ni][3] + bz.y);
            }
        }
    } else {
        // fused rope + fp16 epilogue
        const int nband = n0 + wc * 64;           // warp band start = one head
        const bool is_v = (nband >= 2 * DIMM);
        const float qs = (nband < DIMM) ? 0.125f : 1.0f;   // fold softmax scale into q

        if (is_v) {
#pragma unroll
            for (int mi = 0; mi < 2; mi++) {
                int r0 = m0 + wr * 32 + mi * 16 + g;
#pragma unroll
                for (int ni = 0; ni < 8; ni++) {
                    int c = nband + ni * 8 + 2 * t;
                    float2 bz = *(const float2*)&bias[c];
                    *(unsigned*)&C16[(size_t)r0 * N + c] =
                        packh2(acc[mi][ni][0] + bz.x, acc[mi][ni][1] + bz.y);
                    *(unsigned*)&C16[(size_t)(r0 + 8) * N + c] =
                        packh2(acc[mi][ni][2] + bz.x, acc[mi][ni][3] + bz.y);
                }
            }
        } else {
#pragma unroll
            for (int mi = 0; mi < 2; mi++) {
                int r0 = m0 + wr * 32 + mi * 16 + g;
                int tr0 = r0 & (TT - 1);
                int tr1 = (r0 + 8) & (TT - 1);
#pragma unroll
                for (int ni = 0; ni < 4; ni++) {
                    int c  = nband + ni * 8 + 2 * t;   // d' = ni*8+2t in [0,31)
                    int d0 = (c & 63);                 // < 32
                    float2 bzA = *(const float2*)&bias[c];
                    float2 bzB = *(const float2*)&bias[c + 32];
                    float2 cs00 = tab[(tr0 << 5) | d0];
                    float2 cs01 = tab[(tr0 << 5) | (d0 + 1)];
                    float2 cs10 = tab[(tr1 << 5) | d0];
                    float2 cs11 = tab[(tr1 << 5) | (d0 + 1)];

                    // row r0
                    float a0 = acc[mi][ni][0] + bzA.x,  a1 = acc[mi][ni][1] + bzA.y;
                    float b0 = acc[mi][ni + 4][0] + bzB.x, b1 = acc[mi][ni + 4][1] + bzB.y;
                    *(unsigned*)&C16[(size_t)r0 * N + c] =
                        packh2(qs * (a0 * cs00.x - b0 * cs00.y),
                               qs * (a1 * cs01.x - b1 * cs01.y));
                    *(unsigned*)&C16[(size_t)r0 * N + c + 32] =
                        packh2(qs * (a0 * cs00.y + b0 * cs00.x),
                               qs * (a1 * cs01.y + b1 * cs01.x));

                    // row r0+8
                    a0 = acc[mi][ni][2] + bzA.x;  a1 = acc[mi][ni][3] + bzA.y;
                    b0 = acc[mi][ni + 4][2] + bzB.x; b1 = acc[mi][ni + 4][3] + bzB.y;
                    *(unsigned*)&C16[(size_t)(r0 + 8) * N + c] =
                        packh2(qs * (a0 * cs10.x - b0 * cs10.y),
                               qs * (a1 * cs11.x - b1 * cs11.y));
                    *(unsigned*)&C16[(size_t)(r0 + 8) * N + c + 32] =
                        packh2(qs * (a0 * cs10.y + b0 * cs10.x),
                               qs * (a1 * cs11.y + b1 * cs11.x));
                }
            }
        }
    }
}

// ---------------------------------------------------------------------------
// Flash attention (causal), fp16 mma m16n8k16, cp.async double-buffered K/V,
// ldmatrix fragments, direct S->P fragment pack. q pre-scaled by 1/8.
// ---------------------------------------------------------------------------
__global__ __launch_bounds__(256, 2)
void attn_f16_kernel(const __half* __restrict__ qkvh, __half* __restrict__ y)
{
    extern __shared__ __half sma[];
    __half* Qs = sma;
    __half* Kd = Qs + 128 * ATSP;
    __half* Vd = Kd + 2 * 64 * ATSP;

    const int qb   = gridDim.x - 1 - blockIdx.x;
    const int h    = blockIdx.y;
    const int b    = blockIdx.z;
    const int tid  = threadIdx.x;
    const int wid  = tid >> 5;
    const int lane = tid & 31;
    const int g    = lane >> 2;
    const int t    = lane & 3;

    const __half* base = qkvh + (size_t)b * TT * QKVN + h * DHH;

    {
        const unsigned qd = smem_u32(Qs);
        int r0c = tid >> 3, c0 = (tid & 7) << 3;
#pragma unroll
        for (int l = 0; l < 4; l++) {
            int r = r0c + l * 32;
            CP_ASYNC16(qd + (unsigned)(r * ATSP + c0) * 2,
                       base + (size_t)(qb * 128 + r) * QKVN + c0);
        }
    }

    const unsigned kdb = smem_u32(Kd), vdb = smem_u32(Vd);
    const int nkb = 2 * qb + 2;
    const int srr = tid >> 3, src = (tid & 7) << 3;

    auto issue_kv = [&](int kb, int buf) {
        const unsigned boff = (unsigned)(buf * 64 * ATSP) * 2;
#pragma unroll
        for (int l = 0; l < 2; l++) {
            int r = srr + l * 32;
            size_t gix = (size_t)(kb * 64 + r) * QKVN + src;
            unsigned doff = (unsigned)(r * ATSP + src) * 2;
            CP_ASYNC16(kdb + boff + doff, base + DIMM + gix);
            CP_ASYNC16(vdb + boff + doff, base + 2 * DIMM + gix);
        }
        CP_COMMIT();
    };

    issue_kv(0, 0);
    issue_kv(1, 1);

    const unsigned qfc = smem_u32(Qs) +
        (unsigned)((wid * 16 + (lane & 15)) * ATSP + (lane >> 4) * 8) * 2;
    const unsigned kfc = kdb +
        (unsigned)((((lane >> 4) << 3) + (lane & 7)) * ATSP + ((lane >> 3) & 1) * 8) * 2;
    const unsigned vfc = vdb + (unsigned)(lane * ATSP) * 2;

    float O[8][4];
#pragma unroll
    for (int nf = 0; nf < 8; nf++)
#pragma unroll
        for (int j = 0; j < 4; j++) O[nf][j] = 0.f;
    float m_lo = -1e30f, m_hi = -1e30f, l_lo = 0.f, l_hi = 0.f;

    const int rw0 = qb * 128 + wid * 16;

    for (int kb = 0; kb < nkb; kb++) {
        const int buf = kb & 1;
        if (kb + 1 < nkb) { CP_WAIT1(); } else { CP_WAIT0(); }
        __syncthreads();

        if (kb * 64 <= rw0 + 15) {
            const unsigned boff = (unsigned)(buf * 64 * ATSP) * 2;

            float S[8][4];
#pragma unroll
            for (int nf = 0; nf < 8; nf++)
#pragma unroll
                for (int j = 0; j < 4; j++) S[nf][j] = 0.f;

#pragma unroll
            for (int ks = 0; ks < 4; ks++) {
                unsigned aq[4];
                ldsm_x4(aq, qfc + (unsigned)(ks * 16) * 2);
#pragma unroll
                for (int nfp = 0; nfp < 4; nfp++) {
                    unsigned bk[4];
                    ldsm_x4(bk, kfc + boff +
                            (unsigned)(nfp * 16 * ATSP + ks * 16) * 2);
                    mma_f16(S[2 * nfp],     aq, bk);
                    mma_f16(S[2 * nfp + 1], aq, bk + 2);
                }
            }

            // causal mask (scale already folded into q)
            const int r0 = rw0 + g;
            const int r1 = r0 + 8;
            if (kb * 64 + 63 > rw0) {
#pragma unroll
                for (int nf = 0; nf < 8; nf++) {
                    int c0 = kb * 64 + nf * 8 + 2 * t;
                    if (c0     > r0) S[nf][0] = -1e30f;
                    if (c0 + 1 > r0) S[nf][1] = -1e30f;
                    if (c0     > r1) S[nf][2] = -1e30f;
                    if (c0 + 1 > r1) S[nf][3] = -1e30f;
                }
            }

            float mx0 = -1e30f, mx1 = -1e30f;
#pragma unroll
            for (int nf = 0; nf < 8; nf++) {
                mx0 = fmaxf(mx0, fmaxf(S[nf][0], S[nf][1]));
                mx1 = fmaxf(mx1, fmaxf(S[nf][2], S[nf][3]));
            }
            mx0 = fmaxf(mx0, __shfl_xor_sync(0xffffffffu, mx0, 1));
            mx0 = fmaxf(mx0, __shfl_xor_sync(0xffffffffu, mx0, 2));
            mx1 = fmaxf(mx1, __shfl_xor_sync(0xffffffffu, mx1, 1));
            mx1 = fmaxf(mx1, __shfl_xor_sync(0xffffffffu, mx1, 2));

            float mn0 = fmaxf(m_lo, mx0);
            float mn1 = fmaxf(m_hi, mx1);
            float al0 = __expf(m_lo - mn0);
            float al1 = __expf(m_hi - mn1);
            float rs0 = 0.f, rs1 = 0.f;
#pragma unroll
            for (int nf = 0; nf < 8; nf++) {
                S[nf][0] = __expf(S[nf][0] - mn0);
                S[nf][1] = __expf(S[nf][1] - mn0);
                S[nf][2] = __expf(S[nf][2] - mn1);
                S[nf][3] = __expf(S[nf][3] - mn1);
                rs0 += S[nf][0] + S[nf][1];
                rs1 += S[nf][2] + S[nf][3];
            }
            rs0 += __shfl_xor_sync(0xffffffffu, rs0, 1);
            rs0 += __shfl_xor_sync(0xffffffffu, rs0, 2);
            rs1 += __shfl_xor_sync(0xffffffffu, rs1, 1);
            rs1 += __shfl_xor_sync(0xffffffffu, rs1, 2);
            l_lo = l_lo * al0 + rs0;  m_lo = mn0;
            l_hi = l_hi * al1 + rs1;  m_hi = mn1;
#pragma unroll
            for (int nf = 0; nf < 8; nf++) {
                O[nf][0] *= al0; O[nf][1] *= al0;
                O[nf][2] *= al1; O[nf][3] *= al1;
            }

            unsigned aP[4][4];
#pragma unroll
            for (int ks = 0; ks < 4; ks++) {
                aP[ks][0] = packh2(S[2 * ks][0],     S[2 * ks][1]);
                aP[ks][1] = packh2(S[2 * ks][2],     S[2 * ks][3]);
                aP[ks][2] = packh2(S[2 * ks + 1][0], S[2 * ks + 1][1]);
                aP[ks][3] = packh2(S[2 * ks + 1][2], S[2 * ks + 1][3]);
            }

#pragma unroll
            for (int nf = 0; nf < 8; nf++) {
                unsigned vf[8];
                ldsm_x4t(vf,     vfc + boff + (unsigned)(nf * 8) * 2);
                ldsm_x4t(vf + 4, vfc + boff + (unsigned)(32 * ATSP + nf * 8) * 2);
#pragma unroll
                for (int ks = 0; ks < 4; ks++)
                    mma_f16(O[nf], aP[ks], vf + ((ks & 1) * 2) + ((ks >> 1) * 4));
            }
        }

        __syncthreads();
        if (kb + 2 < nkb) issue_kv(kb + 2, buf);
    }

    const float inv0 = 1.0f / l_lo;
    const float inv1 = 1.0f / l_hi;
    const int r0 = rw0 + g;
    const int r1 = r0 + 8;
    __half* yr0 = y + ((size_t)b * TT + r0) * DIMM + h * DHH;
    __half* yr1 = y + ((size_t)b * TT + r1) * DIMM + h * DHH;
#pragma unroll
    for (int nf = 0; nf < 8; nf++) {
        int c = nf * 8 + 2 * t;
        *(unsigned*)&yr0[c] = packh2(O[nf][0] * inv0, O[nf][1] * inv0);
        *(unsigned*)&yr1[c] = packh2(O[nf][2] * inv1, O[nf][3] * inv1);
    }
}

// ---------------------------------------------------------------------------
extern "C" void kernel_launch(void* const* d_in, const int* in_sizes, int n_in,
                              void* d_out, int out_size)
{
    const float* x     = (const float*)d_in[0];
    const float* W_qkv = (const float*)d_in[2];
    const float* b_qkv = (const float*)d_in[3];
    const float* W_out = (const float*)d_in[4];
    const float* b_out = (const float*)d_in[5];
    float* out = (float*)d_out;

    float2* rope;
    __half *qkvh, *y, *xh, *wqkvh, *wouth;
    cudaGetSymbolAddress((void**)&qkvh, g_qkvh);
    cudaGetSymbolAddress((void**)&y, g_y);
    cudaGetSymbolAddress((void**)&xh, g_xh);
    cudaGetSymbolAddress((void**)&wqkvh, g_wqkvh);
    cudaGetSymbolAddress((void**)&wouth, g_wouth);
    cudaGetSymbolAddress((void**)&rope, g_rope);

    const int gemm_smem = 3 * GSTGH * 2;
    cudaFuncSetAttribute(gemm_f16_kernel<0>,
                         cudaFuncAttributeMaxDynamicSharedMemorySize, gemm_smem);
    cudaFuncSetAttribute(gemm_f16_kernel<1>,
                         cudaFuncAttributeMaxDynamicSharedMemorySize, gemm_smem);
    const int attn_smem = (128 + 4 * 64) * ATSP * 2;
    cudaFuncSetAttribute(attn_f16_kernel,
                         cudaFuncAttributeMaxDynamicSharedMemorySize, attn_smem);

    // 0) convert x/W_qkv/W_out to fp16 (one launch) + rope table
    convert_all_kernel<<<(NX4 + NW14 + NW24 + 255) / 256, 256>>>(
        x, xh, W_qkv, wqkvh, W_out, wouth);
    rope_table_kernel<<<(TT * 32 + 255) / 256, 256>>>(rope);

    // 1) qkvh = rope(xh @ wqkvh + b_qkv), fp16, q pre-scaled by 1/8
    gemm_f16_kernel<1><<<dim3(QKVN / 128, MROWS / 128), 256, gemm_smem>>>(
        xh, wqkvh, b_qkv, nullptr, qkvh, rope, MROWS, QKVN, DIMM);

    // 2) causal flash attention -> y (fp16)
    attn_f16_kernel<<<dim3(TT / 128, HH, BB), 256, attn_smem>>>(qkvh, y);

    // 3) out = y @ wouth + b_out (fp32)
    gemm_f16_kernel<0><<<dim3(DIMM / 128, MROWS / 128), 256, gemm_smem>>>(
        y, wouth, b_out, out, nullptr, nullptr, MROWS, DIMM, DIMM);
}